// round 12
// baseline (speedup 1.0000x reference)
#include <cuda_runtime.h>
#include <math.h>

// ---------------------------------------------------------------------------
// CausalSelfAttention: x -> (QKV proj + RoPE) -> flash attention -> out proj
// B=2, T=2048, C=1024, nh=16, hs=64. fp32, packed f32x2 (FFMA2) math.
// R9: back to 256-thr/8x8 GEMMs (R6 best) + duplicated-B smem so the fma2
// broadcast operand loads directly (no bc2 MOVs on the fma pipe).
// Attention: no-max softmax, dup-K/dup-V, no reg cap (avoid R6 spills).
// ---------------------------------------------------------------------------

#define NH     16
#define HS     64
#define TSEQ   2048
#define CEMB   1024
#define BROWS  4096
#define LN1E4  9.210340371976184f
#define ASTR   132            // A smem row stride (words)
#define BSTR   292            // dup-B smem row stride (words); 2 blocks of 144
#define QSTR   132            // attn Q/P smem row stride
#define KD     148            // attn dup-K/dup-V row stride (words)

// word offset of dup'd col-group t (0..15) inside a 64-col dup block;
// +4-per-4-group offset halves bank conflicts (4-way -> 2-way = floor)
#define DUPB(t) (8 * (t) + 4 * (((t) >> 2) & 3))

typedef unsigned long long u64;

// ---- packed f32x2 helpers (sm_100+ PTX) -----------------------------------
__device__ __forceinline__ void fma2(u64& c, u64 a, u64 b) {
    asm("fma.rn.f32x2 %0, %1, %2, %0;" : "+l"(c) : "l"(a), "l"(b));
}
__device__ __forceinline__ void add2(u64& c, u64 a) {
    asm("add.rn.f32x2 %0, %0, %1;" : "+l"(c) : "l"(a));
}
__device__ __forceinline__ u64 bc2(float v) {
    u64 r; asm("mov.b64 %0, {%1, %1};" : "=l"(r) : "f"(v)); return r;
}
__device__ __forceinline__ u64 pk2(float lo, float hi) {
    u64 r; asm("mov.b64 %0, {%1, %2};" : "=l"(r) : "f"(lo), "f"(hi)); return r;
}
__device__ __forceinline__ float2 up2(u64 v) {
    float2 f; asm("mov.b64 {%0, %1}, %2;" : "=f"(f.x), "=f"(f.y) : "l"(v)); return f;
}

// Scratch (allocation-free): Q/K/V in (b,h,t,d) layout, y in (b,t,c) layout.
__device__ __align__(16) float g_q[2 * NH * TSEQ * HS];
__device__ __align__(16) float g_k[2 * NH * TSEQ * HS];
__device__ __align__(16) float g_v[2 * NH * TSEQ * HS];
__device__ __align__(16) float g_y[2 * TSEQ * CEMB];

// Stage A slice: 8 k-values of row rs_ (transposed layout).
__device__ __forceinline__ void stageA(float* S, int ks_, int rs_,
                                       float4 a0, float4 a1)
{
    S[(ks_ + 0) * ASTR + rs_] = a0.x;
    S[(ks_ + 1) * ASTR + rs_] = a0.y;
    S[(ks_ + 2) * ASTR + rs_] = a0.z;
    S[(ks_ + 3) * ASTR + rs_] = a0.w;
    S[(ks_ + 4) * ASTR + rs_] = a1.x;
    S[(ks_ + 5) * ASTR + rs_] = a1.y;
    S[(ks_ + 6) * ASTR + rs_] = a1.z;
    S[(ks_ + 7) * ASTR + rs_] = a1.w;
}

// Stage dup-B slice: 8 k-values of col rs_, each duplicated as u64.
__device__ __forceinline__ void stageB(float* S, int ks_, int rs_,
                                       float4 b0, float4 b1)
{
    const int blk = rs_ >> 6;
    const int cw  = rs_ & 63;
    const int w   = blk * 144 + DUPB(cw >> 2) + 2 * (cw & 3);
    *(u64*)&S[(ks_ + 0) * BSTR + w] = bc2(b0.x);
    *(u64*)&S[(ks_ + 1) * BSTR + w] = bc2(b0.y);
    *(u64*)&S[(ks_ + 2) * BSTR + w] = bc2(b0.z);
    *(u64*)&S[(ks_ + 3) * BSTR + w] = bc2(b0.w);
    *(u64*)&S[(ks_ + 4) * BSTR + w] = bc2(b1.x);
    *(u64*)&S[(ks_ + 5) * BSTR + w] = bc2(b1.y);
    *(u64*)&S[(ks_ + 6) * BSTR + w] = bc2(b1.z);
    *(u64*)&S[(ks_ + 7) * BSTR + w] = bc2(b1.w);
}

// ---------------------------------------------------------------------------
// Kernel 1: QKV projection.  out[r,c] = sum_k x[r,k] * W[c,k] + b[c]
// 128x128 tile, BK=16, 256 threads, 8x8 microtile, dup-B (MOV-free fma2).
// Double-buffered smem, one __syncthreads per K-tile.
// ---------------------------------------------------------------------------
__global__ __launch_bounds__(256, 2) void qkv_gemm(
    const float* __restrict__ x,
    const float* __restrict__ Wq, const float* __restrict__ bq,
    const float* __restrict__ Wk, const float* __restrict__ bk,
    const float* __restrict__ Wv, const float* __restrict__ bv)
{
    const int z = blockIdx.z;
    const float* W    = (z == 0) ? Wq : (z == 1) ? Wk : Wv;
    const float* bias = (z == 0) ? bq : (z == 1) ? bk : bv;
    float* out        = (z == 0) ? g_q : (z == 1) ? g_k : g_v;

    __shared__ __align__(16) float As[2][16 * ASTR];
    __shared__ __align__(16) float Bs[2][16 * BSTR];

    const int tid = threadIdx.x;
    const int tx = tid & 15, ty = tid >> 4;
    const int row0 = blockIdx.y * 128;
    const int col0 = blockIdx.x * 128;

    const int rs_ = tid >> 1;           // staging row/col 0..127
    const int ks_ = (tid & 1) * 8;      // staging k offset

    const float* ap = x + (size_t)(row0 + rs_) * CEMB + ks_;
    const float* bp = W + (size_t)(col0 + rs_) * CEMB + ks_;

    u64 acc[4][8];
    #pragma unroll
    for (int p = 0; p < 4; p++)
        #pragma unroll
        for (int j = 0; j < 8; j++) acc[p][j] = 0ULL;

    float4 pa0 = *(const float4*)(ap);
    float4 pa1 = *(const float4*)(ap + 4);
    float4 pb0 = *(const float4*)(bp);
    float4 pb1 = *(const float4*)(bp + 4);
    stageA(&As[0][0], ks_, rs_, pa0, pa1);
    stageB(&Bs[0][0], ks_, rs_, pb0, pb1);
    __syncthreads();

    const int bbase0 = DUPB(tx);        // dup block 0 word offset for this lane
    int buf = 0;
    #pragma unroll 1
    for (int kt = 0; kt < CEMB; kt += 16) {
        const bool more = (kt + 16 < CEMB);
        if (more) {                     // prefetch next tile under compute
            pa0 = *(const float4*)(ap + kt + 16);
            pa1 = *(const float4*)(ap + kt + 20);
            pb0 = *(const float4*)(bp + kt + 16);
            pb1 = *(const float4*)(bp + kt + 20);
        }
        const float* Ac = &As[buf][0];
        const float* Bc = &Bs[buf][0];
        #pragma unroll
        for (int kk = 0; kk < 16; kk++) {
            const float* abase = Ac + kk * ASTR + ty * 4;
            ulonglong2 aA = *(const ulonglong2*)abase;        // rows ty*4+0..3
            ulonglong2 aB = *(const ulonglong2*)(abase + 64); // rows 64+ty*4..
            const float* bb0p = Bc + kk * BSTR + bbase0;
            ulonglong2 b01 = *(const ulonglong2*)(bb0p);      // cols 4tx,4tx+1
            ulonglong2 b23 = *(const ulonglong2*)(bb0p + 4);  // cols 4tx+2,+3
            ulonglong2 b45 = *(const ulonglong2*)(bb0p + 144);
            ulonglong2 b67 = *(const ulonglong2*)(bb0p + 148);
            u64 aa[4] = {aA.x, aA.y, aB.x, aB.y};
            u64 bb[8] = {b01.x, b01.y, b23.x, b23.y,
                         b45.x, b45.y, b67.x, b67.y};
            #pragma unroll
            for (int p = 0; p < 4; p++)
                #pragma unroll
                for (int j = 0; j < 8; j++)
                    fma2(acc[p][j], aa[p], bb[j]);
        }
        if (more) {
            stageA(&As[buf ^ 1][0], ks_, rs_, pa0, pa1);
            stageB(&Bs[buf ^ 1][0], ks_, rs_, pb0, pb1);
            __syncthreads();
            buf ^= 1;
        }
    }

    // Epilogue: bias, RoPE (Q,K), scatter to (b, h, t, d).
    float4 bb0 = *(const float4*)&bias[col0 + tx * 4];
    float4 bb1 = *(const float4*)&bias[col0 + 64 + tx * 4];
    float bvv[8] = {bb0.x, bb0.y, bb0.z, bb0.w, bb1.x, bb1.y, bb1.z, bb1.w};

    const int d0 = tx * 4;
    const int h0 = blockIdx.x * 2;
    float th0 = 0.f, th1 = 0.f;
    if (z < 2) {
        th0 = expf(-((float)d0)       * (LN1E4 / 64.0f));
        th1 = expf(-((float)(d0 + 2)) * (LN1E4 / 64.0f));
    }

    #pragma unroll
    for (int p = 0; p < 4; p++) {
        #pragma unroll
        for (int e = 0; e < 2; e++) {
            float v[8];
            #pragma unroll
            for (int j = 0; j < 8; j++) {
                float2 f = up2(acc[p][j]);
                v[j] = ((e == 0) ? f.x : f.y) + bvv[j];
            }
            int rl = ((p >> 1) << 6) + ty * 4 + ((p & 1) << 1) + e;
            int row = row0 + rl;
            int b = row >> 11;
            int t = row & 2047;
            if (z < 2) {
                float c0, s0, c1, s1;
                sincosf((float)t * th0, &s0, &c0);
                sincosf((float)t * th1, &s1, &c1);
                float r0 = v[0] * c0 - v[1] * s0, r1 = v[0] * s0 + v[1] * c0;
                float r2 = v[2] * c1 - v[3] * s1, r3 = v[2] * s1 + v[3] * c1;
                float r4 = v[4] * c0 - v[5] * s0, r5 = v[4] * s0 + v[5] * c0;
                float r6 = v[6] * c1 - v[7] * s1, r7 = v[6] * s1 + v[7] * c1;
                v[0] = r0; v[1] = r1; v[2] = r2; v[3] = r3;
                v[4] = r4; v[5] = r5; v[6] = r6; v[7] = r7;
            }
            float4 o0 = {v[0], v[1], v[2], v[3]};
            float4 o1 = {v[4], v[5], v[6], v[7]};
            *(float4*)&out[(((size_t)b * NH + h0) * TSEQ + t) * HS + d0] = o0;
            *(float4*)&out[(((size_t)b * NH + h0 + 1) * TSEQ + t) * HS + d0] = o1;
        }
    }
}

// ---------------------------------------------------------------------------
// Kernel 2: flash attention (fp32/FFMA2, causal), no-max softmax
// (scores bounded ~|q||k|/8, exp safe in fp32, l reduced once at the end).
// Br=128, Bc=64. 256 threads, 8q x 4k microtile, dup-K / dup-V smem.
// ---------------------------------------------------------------------------
#define ATTN_SMEM ((64 * QSTR * 2 + 64 * KD * 2) * 4)   // 143360 bytes

__global__ __launch_bounds__(256) void attn_kernel()
{
    extern __shared__ __align__(16) float sm[];
    float* Qs = sm;                  // [d][q]   64 x 132, pre-scaled
    float* Ks = Qs + 64 * QSTR;      // [d][2k]  64 x 148  (dup'd keys)
    float* Ps = Ks + 64 * KD;        // [k][q]   64 x 132
    float* Vs = Ps + 64 * QSTR;      // [k][2d]  64 x 148  (dup'd dims)

    const int tid = threadIdx.x;
    const int tx = tid & 15, ty = tid >> 4;
    const int qt = (gridDim.x - 1) - blockIdx.x;    // heavy tiles first
    const int bh = blockIdx.y;

    const float* qp = g_q + (size_t)bh * TSEQ * HS;
    const float* kp = g_k + (size_t)bh * TSEQ * HS;
    const float* vp = g_v + (size_t)bh * TSEQ * HS;

    const int q0 = qt * 128;

    // Load Q tile transposed, pre-scaled by 1/sqrt(hs)
    #pragma unroll
    for (int jj = 0; jj < 8; jj++) {
        int idx = tid + jj * 256;
        int r = idx >> 4;
        int c4 = (idx & 15) * 4;
        float4 qv = *(const float4*)&qp[(size_t)(q0 + r) * HS + c4];
        Qs[(c4 + 0) * QSTR + r] = qv.x * 0.125f;
        Qs[(c4 + 1) * QSTR + r] = qv.y * 0.125f;
        Qs[(c4 + 2) * QSTR + r] = qv.z * 0.125f;
        Qs[(c4 + 3) * QSTR + r] = qv.w * 0.125f;
    }

    // Stage K/V tile 0 (dup layout)
    float4 kreg[4], vreg[4];
    #pragma unroll
    for (int jj = 0; jj < 4; jj++) {
        int idx = tid + jj * 256;
        int r = idx >> 4;
        int c4 = (idx & 15) * 4;
        kreg[jj] = *(const float4*)&kp[(size_t)r * HS + c4];
        vreg[jj] = *(const float4*)&vp[(size_t)r * HS + c4];
    }
    #pragma unroll
    for (int jj = 0; jj < 4; jj++) {
        int idx = tid + jj * 256;
        int r = idx >> 4;                       // key index
        int c4 = (idx & 15) * 4;                // dim base
        int wk = DUPB(r >> 2) + 2 * (r & 3);    // key dup word
        *(u64*)&Ks[(c4 + 0) * KD + wk] = bc2(kreg[jj].x);
        *(u64*)&Ks[(c4 + 1) * KD + wk] = bc2(kreg[jj].y);
        *(u64*)&Ks[(c4 + 2) * KD + wk] = bc2(kreg[jj].z);
        *(u64*)&Ks[(c4 + 3) * KD + wk] = bc2(kreg[jj].w);
        int wv = DUPB(idx & 15);                // dim-group dup word
        ulonglong2 v01 = {bc2(vreg[jj].x), bc2(vreg[jj].y)};
        ulonglong2 v23 = {bc2(vreg[jj].z), bc2(vreg[jj].w)};
        *(ulonglong2*)&Vs[r * KD + wv]     = v01;
        *(ulonglong2*)&Vs[r * KD + wv + 4] = v23;
    }

    u64 O[4][4];                     // [q-row-pair][d-col], packed f32x2
    u64 l2[4];                       // packed per-lane partial row sums
    #pragma unroll
    for (int p = 0; p < 4; p++) {
        l2[p] = 0ULL;
        #pragma unroll
        for (int j = 0; j < 4; j++) O[p][j] = 0ULL;
    }

    const int bdup = DUPB(tx);
    const int ktmax = 2 * qt + 1;
    __syncthreads();

    for (int kt = 0; kt <= ktmax; kt++) {
        // S = (Q/8) K^T, packed over q-row pairs
        u64 s2[4][4];
        #pragma unroll
        for (int p = 0; p < 4; p++)
            #pragma unroll
            for (int j = 0; j < 4; j++) s2[p][j] = 0ULL;
        #pragma unroll 8
        for (int d = 0; d < 64; d++) {
            const float* qb = &Qs[d * QSTR + ty * 4];
            ulonglong2 aA = *(const ulonglong2*)qb;
            ulonglong2 aB = *(const ulonglong2*)(qb + 64);
            const float* kb = &Ks[d * KD + bdup];
            ulonglong2 k01 = *(const ulonglong2*)kb;
            ulonglong2 k23 = *(const ulonglong2*)(kb + 4);
            u64 aa[4] = {aA.x, aA.y, aB.x, aB.y};
            u64 bb[4] = {k01.x, k01.y, k23.x, k23.y};
            #pragma unroll
            for (int p = 0; p < 4; p++)
                #pragma unroll
                for (int j = 0; j < 4; j++)
                    fma2(s2[p][j], aa[p], bb[j]);
        }

        // Prefetch next K/V tile into registers (hidden under exp + PV)
        if (kt < ktmax) {
            const int kn = (kt + 1) * 64;
            #pragma unroll
            for (int jj = 0; jj < 4; jj++) {
                int idx = tid + jj * 256;
                int r = idx >> 4;
                int c4 = (idx & 15) * 4;
                kreg[jj] = *(const float4*)&kp[(size_t)(kn + r) * HS + c4];
                vreg[jj] = *(const float4*)&vp[(size_t)(kn + r) * HS + c4];
            }
        }

        // exp (no max subtraction), causal mask, l accumulate, store P
        const int k0 = kt * 64;
        const bool diag = (kt >= 2 * qt);
        #pragma unroll
        for (int p = 0; p < 4; p++) {
            float2 f[4];
            #pragma unroll
            for (int j = 0; j < 4; j++) f[j] = up2(s2[p][j]);
            const int rb = ((p >> 1) << 6) + ty * 4 + ((p & 1) << 1);
            if (diag) {
                const int r0 = q0 + rb, r1 = r0 + 1;
                #pragma unroll
                for (int j = 0; j < 4; j++) {
                    int c = k0 + tx * 4 + j;
                    if (c > r0) f[j].x = -1e30f;
                    if (c > r1) f[j].y = -1e30f;
                }
            }
            #pragma unroll
            for (int j = 0; j < 4; j++) {
                u64 pe = pk2(__expf(f[j].x), __expf(f[j].y));
                add2(l2[p], pe);
                *(u64*)&Ps[(tx * 4 + j) * QSTR + rb] = pe;
            }
        }
        __syncthreads();             // Ps visible; everyone done with Ks

        // O += P V
        #pragma unroll 8
        for (int kk = 0; kk < 64; kk++) {
            const float* pb = &Ps[kk * QSTR + ty * 4];
            ulonglong2 aA = *(const ulonglong2*)pb;
            ulonglong2 aB = *(const ulonglong2*)(pb + 64);
            const float* vb = &Vs[kk * KD + bdup];
            ulonglong2 v01 = *(const ulonglong2*)vb;
            ulonglong2 v23 = *(const ulonglong2*)(vb + 4);
            u64 aa[4] = {aA.x, aA.y, aB.x, aB.y};
            u64 bb[4] = {v01.x, v01.y, v23.x, v23.y};
            #pragma unroll
            for (int p = 0; p < 4; p++)
                #pragma unroll
                for (int j = 0; j < 4; j++)
                    fma2(O[p][j], aa[p], bb[j]);
        }
        __syncthreads();             // Vs/Ps reads done

        if (kt < ktmax) {            // stage next tile (dup layout)
            #pragma unroll
            for (int jj = 0; jj < 4; jj++) {
                int idx = tid + jj * 256;
                int r = idx >> 4;
                int c4 = (idx & 15) * 4;
                int wk = DUPB(r >> 2) + 2 * (r & 3);
                *(u64*)&Ks[(c4 + 0) * KD + wk] = bc2(kreg[jj].x);
                *(u64*)&Ks[(c4 + 1) * KD + wk] = bc2(kreg[jj].y);
                *(u64*)&Ks[(c4 + 2) * KD + wk] = bc2(kreg[jj].z);
                *(u64*)&Ks[(c4 + 3) * KD + wk] = bc2(kreg[jj].w);
                int wv = DUPB(idx & 15);
                ulonglong2 v01 = {bc2(vreg[jj].x), bc2(vreg[jj].y)};
                ulonglong2 v23 = {bc2(vreg[jj].z), bc2(vreg[jj].w)};
                *(ulonglong2*)&Vs[r * KD + wv]     = v01;
                *(ulonglong2*)&Vs[r * KD + wv + 4] = v23;
            }
            __syncthreads();         // staging visible for next S
        }
    }

    // Final l reduction across the 16 tx lanes (once)
    float l[8];
    #pragma unroll
    for (int p = 0; p < 4; p++) {
        float2 f = up2(l2[p]);
        l[2 * p] = f.x;
        l[2 * p + 1] = f.y;
    }
    #pragma unroll
    for (int i = 0; i < 8; i++)
        #pragma unroll
        for (int off = 8; off >= 1; off >>= 1)
            l[i] += __shfl_xor_sync(0xffffffffu, l[i], off);

    // Normalize, write y in (b, t, c) layout for the output projection
    const int b = bh >> 4, h = bh & 15;
    #pragma unroll
    for (int p = 0; p < 4; p++) {
        float2 f0 = up2(O[p][0]);
        float2 f1 = up2(O[p][1]);
        float2 f2 = up2(O[p][2]);
        float2 f3 = up2(O[p][3]);
        int i0 = 2 * p;
        float inv0 = 1.0f / l[i0];
        float inv1 = 1.0f / l[i0 + 1];
        int t0 = q0 + ((i0 >> 2) << 6) + ty * 4 + (i0 & 3);
        float4 o0 = {f0.x * inv0, f1.x * inv0, f2.x * inv0, f3.x * inv0};
        float4 o1 = {f0.y * inv1, f1.y * inv1, f2.y * inv1, f3.y * inv1};
        *(float4*)&g_y[((size_t)b * TSEQ + t0) * CEMB + h * HS + tx * 4] = o0;
        *(float4*)&g_y[((size_t)b * TSEQ + t0 + 1) * CEMB + h * HS + tx * 4] = o1;
    }
}

// ---------------------------------------------------------------------------
// Kernel 3: output projection. Same dup-B FFMA2 GEMM, bias epilogue.
// ---------------------------------------------------------------------------
__global__ __launch_bounds__(256, 2) void proj_gemm(
    const float* __restrict__ Wp, const float* __restrict__ bp,
    float* __restrict__ out)
{
    __shared__ __align__(16) float As[2][16 * ASTR];
    __shared__ __align__(16) float Bs[2][16 * BSTR];

    const int tid = threadIdx.x;
    const int tx = tid & 15, ty = tid >> 4;
    const int row0 = blockIdx.y * 128;
    const int col0 = blockIdx.x * 128;

    const int rs_ = tid >> 1;
    const int ks_ = (tid & 1) * 8;

    const float* ap = g_y + (size_t)(row0 + rs_) * CEMB + ks_;
    const float* bpW = Wp + (size_t)(col0 + rs_) * CEMB + ks_;

    u64 acc[4][8];
    #pragma unroll
    for (int p = 0; p < 4; p++)
        #pragma unroll
        for (int j = 0; j < 8; j++) acc[p][j] = 0ULL;

    float4 pa0 = *(const float4*)(ap);
    float4 pa1 = *(const float4*)(ap + 4);
    float4 pb0 = *(const float4*)(bpW);
    float4 pb1 = *(const float4*)(bpW + 4);
    stageA(&As[0][0], ks_, rs_, pa0, pa1);
    stageB(&Bs[0][0], ks_, rs_, pb0, pb1);
    __syncthreads();

    const int bbase0 = DUPB(tx);
    int buf = 0;
    #pragma unroll 1
    for (int kt = 0; kt < CEMB; kt += 16) {
        const bool more = (kt + 16 < CEMB);
        if (more) {
            pa0 = *(const float4*)(ap + kt + 16);
            pa1 = *(const float4*)(ap + kt + 20);
            pb0 = *(const float4*)(bpW + kt + 16);
            pb1 = *(const float4*)(bpW + kt + 20);
        }
        const float* Ac = &As[buf][0];
        const float* Bc = &Bs[buf][0];
        #pragma unroll
        for (int kk = 0; kk < 16; kk++) {
            const float* abase = Ac + kk * ASTR + ty * 4;
            ulonglong2 aA = *(const ulonglong2*)abase;
            ulonglong2 aB = *(const ulonglong2*)(abase + 64);
            const float* bb0p = Bc + kk * BSTR + bbase0;
            ulonglong2 b01 = *(const ulonglong2*)(bb0p);
            ulonglong2 b23 = *(const ulonglong2*)(bb0p + 4);
            ulonglong2 b45 = *(const ulonglong2*)(bb0p + 144);
            ulonglong2 b67 = *(const ulonglong2*)(bb0p + 148);
            u64 aa[4] = {aA.x, aA.y, aB.x, aB.y};
            u64 bb[8] = {b01.x, b01.y, b23.x, b23.y,
                         b45.x, b45.y, b67.x, b67.y};
            #pragma unroll
            for (int p = 0; p < 4; p++)
                #pragma unroll
                for (int j = 0; j < 8; j++)
                    fma2(acc[p][j], aa[p], bb[j]);
        }
        if (more) {
            stageA(&As[buf ^ 1][0], ks_, rs_, pa0, pa1);
            stageB(&Bs[buf ^ 1][0], ks_, rs_, pb0, pb1);
            __syncthreads();
            buf ^= 1;
        }
    }

    float4 bb0 = *(const float4*)&bp[col0 + tx * 4];
    float4 bb1 = *(const float4*)&bp[col0 + 64 + tx * 4];
    float bvv[8] = {bb0.x, bb0.y, bb0.z, bb0.w, bb1.x, bb1.y, bb1.z, bb1.w};

    #pragma unroll
    for (int p = 0; p < 4; p++) {
        #pragma unroll
        for (int e = 0; e < 2; e++) {
            float v[8];
            #pragma unroll
            for (int j = 0; j < 8; j++) {
                float2 f = up2(acc[p][j]);
                v[j] = ((e == 0) ? f.x : f.y) + bvv[j];
            }
            int rl = ((p >> 1) << 6) + ty * 4 + ((p & 1) << 1) + e;
            size_t row = (size_t)(row0 + rl);
            float4 o0 = {v[0], v[1], v[2], v[3]};
            float4 o1 = {v[4], v[5], v[6], v[7]};
            *(float4*)&out[row * CEMB + col0 + tx * 4] = o0;
            *(float4*)&out[row * CEMB + col0 + 64 + tx * 4] = o1;
        }
    }
}

// ---------------------------------------------------------------------------
extern "C" void kernel_launch(void* const* d_in, const int* in_sizes, int n_in,
                              void* d_out, int out_size)
{
    const float* x  = (const float*)d_in[0];
    const float* Wq = (const float*)d_in[1];
    const float* bq = (const float*)d_in[2];
    const float* Wk = (const float*)d_in[3];
    const float* bk = (const float*)d_in[4];
    const float* Wv = (const float*)d_in[5];
    const float* bv = (const float*)d_in[6];
    const float* Wp = (const float*)d_in[7];
    const float* bp = (const float*)d_in[8];
    float* out = (float*)d_out;

    cudaFuncSetAttribute(attn_kernel,
                         cudaFuncAttributeMaxDynamicSharedMemorySize, ATTN_SMEM);

    qkv_gemm<<<dim3(CEMB / 128, BROWS / 128, 3), 256>>>(x, Wq, bq, Wk, bk, Wv, bv);
    attn_kernel<<<dim3(TSEQ / 128, 2 * NH), 256, ATTN_SMEM>>>();
    proj_gemm<<<dim3(CEMB / 128, BROWS / 128), 256>>>(Wp, bp, out);
}

// round 13
// speedup vs baseline: 1.5061x; 1.5061x over previous
#include <cuda_runtime.h>
#include <cuda_bf16.h>
#include <mma.h>
#include <math.h>

using namespace nvcuda;

// ---------------------------------------------------------------------------
// CausalSelfAttention: x -> (QKV proj + RoPE) -> flash attention -> out proj
// B=2, T=2048, C=1024, nh=16, hs=64.
// R13: GEMMs on tensor cores via wmma bf16 with 2-term split (hi+lo), 3 mma
// passes (hi*hi + hi*lo + lo*hi) -> fp32-grade accuracy (~1e-5 rel).
// Attention: fp32 FFMA2, no-max softmax, plain smem layout, no reg cap.
// ---------------------------------------------------------------------------

#define NH     16
#define HS     64
#define TSEQ   2048
#define CEMB   1024
#define BROWS  4096
#define LN1E4  9.210340371976184f
#define LDK    40             // bf16 leading dim of stage tiles (80B rows)
#define QSTR   132            // attn Q/P smem row stride (floats)
#define KSTR   68             // attn K/V smem row stride (floats)
#define CLD    132            // epilogue C smem row stride (floats)

// GEMM smem: 2 stages x (Ahi|Alo|Bhi|Blo), each 128*LDK bf16 = 10240 B
#define STAGE_BYTES  (4 * 128 * LDK * 2)          // 40960
#define GSMEM        (2 * STAGE_BYTES)            // 81920 (>= C: 128*CLD*4)

typedef unsigned long long u64;

// ---- packed f32x2 helpers (sm_100+ PTX) -----------------------------------
__device__ __forceinline__ void fma2(u64& c, u64 a, u64 b) {
    asm("fma.rn.f32x2 %0, %1, %2, %0;" : "+l"(c) : "l"(a), "l"(b));
}
__device__ __forceinline__ void add2(u64& c, u64 a) {
    asm("add.rn.f32x2 %0, %0, %1;" : "+l"(c) : "l"(a));
}
__device__ __forceinline__ u64 bc2(float v) {
    u64 r; asm("mov.b64 %0, {%1, %1};" : "=l"(r) : "f"(v)); return r;
}
__device__ __forceinline__ u64 pk2(float lo, float hi) {
    u64 r; asm("mov.b64 %0, {%1, %2};" : "=l"(r) : "f"(lo), "f"(hi)); return r;
}
__device__ __forceinline__ float2 up2(u64 v) {
    float2 f; asm("mov.b64 {%0, %1}, %2;" : "=f"(f.x), "=f"(f.y) : "l"(v)); return f;
}
// pack two floats to bf16x2 (x0 -> low half / first element in memory)
__device__ __forceinline__ unsigned cvt2(float x0, float x1) {
    unsigned u;
    asm("cvt.rn.bf16x2.f32 %0, %1, %2;" : "=r"(u) : "f"(x1), "f"(x0));
    return u;
}

// Scratch (allocation-free): Q/K/V in (b,h,t,d) layout, y in (b,t,c) layout.
__device__ __align__(16) float g_q[2 * NH * TSEQ * HS];
__device__ __align__(16) float g_k[2 * NH * TSEQ * HS];
__device__ __align__(16) float g_v[2 * NH * TSEQ * HS];
__device__ __align__(16) float g_y[2 * TSEQ * CEMB];

// Convert 16 fp32 -> split bf16 (hi, lo), store 32B each to smem.
// off = elem offset (row*LDK + ko); rows are 80B so 16B alignment holds.
__device__ __forceinline__ void cvtstore16(const float4* v,
                                           __nv_bfloat16* H, __nv_bfloat16* L,
                                           int off)
{
    unsigned uh[8], ul[8];
    #pragma unroll
    for (int q = 0; q < 4; q++) {
        float a = v[q].x, b = v[q].y, c = v[q].z, d = v[q].w;
        unsigned h0 = cvt2(a, b), h1 = cvt2(c, d);
        uh[2 * q] = h0; uh[2 * q + 1] = h1;
        float r0 = a - __uint_as_float(h0 << 16);
        float r1 = b - __uint_as_float(h0 & 0xffff0000u);
        float r2 = c - __uint_as_float(h1 << 16);
        float r3 = d - __uint_as_float(h1 & 0xffff0000u);
        ul[2 * q] = cvt2(r0, r1); ul[2 * q + 1] = cvt2(r2, r3);
    }
    *(uint4*)(H + off)     = make_uint4(uh[0], uh[1], uh[2], uh[3]);
    *(uint4*)(H + off + 8) = make_uint4(uh[4], uh[5], uh[6], uh[7]);
    *(uint4*)(L + off)     = make_uint4(ul[0], ul[1], ul[2], ul[3]);
    *(uint4*)(L + off + 8) = make_uint4(ul[4], ul[5], ul[6], ul[7]);
}

// ---------------------------------------------------------------------------
// Split-bf16 wmma mainloop (shared by both GEMMs).
// C[r,c] = sum_k A[r,k] * Bw[c,k];  A,Bw row-major fp32, K = CEMB.
// 128x128 CTA tile, 256 threads (8 warps as 4x2), result left in smem Cs.
// ---------------------------------------------------------------------------
__device__ __forceinline__ void gemm_mainloop_to_smem(
    char* smemc, const float* __restrict__ Ag, const float* __restrict__ Bg,
    int row0, int col0)
{
    const int tid = threadIdx.x;
    const int wid = tid >> 5;
    const int wr = wid >> 1;            // warp row 0..3  (32 rows each)
    const int wc = wid & 1;             // warp col 0..1  (64 cols each)

    const int ra = tid >> 1;            // staging row/col 0..127
    const int ko = (tid & 1) * 16;      // staging k offset 0/16

    const float* apg = Ag + (size_t)(row0 + ra) * CEMB + ko;
    const float* bpg = Bg + (size_t)(col0 + ra) * CEMB + ko;

    wmma::fragment<wmma::accumulator, 16, 16, 16, float> acc[2][4];
    #pragma unroll
    for (int i = 0; i < 2; i++)
        #pragma unroll
        for (int j = 0; j < 4; j++) wmma::fill_fragment(acc[i][j], 0.0f);

    float4 pa[4], pb[4];
    #pragma unroll
    for (int q = 0; q < 4; q++) {
        pa[q] = *(const float4*)(apg + 4 * q);
        pb[q] = *(const float4*)(bpg + 4 * q);
    }
    {
        __nv_bfloat16* base = (__nv_bfloat16*)smemc;
        cvtstore16(pa, base,               base + 128 * LDK,     ra * LDK + ko);
        cvtstore16(pb, base + 2 * 128 * LDK, base + 3 * 128 * LDK, ra * LDK + ko);
    }
    __syncthreads();

    int buf = 0;
    #pragma unroll 1
    for (int kc = 0; kc < CEMB; kc += 32) {
        const bool more = (kc + 32 < CEMB);
        if (more) {
            #pragma unroll
            for (int q = 0; q < 4; q++) {
                pa[q] = *(const float4*)(apg + kc + 32 + 4 * q);
                pb[q] = *(const float4*)(bpg + kc + 32 + 4 * q);
            }
        }
        const __nv_bfloat16* Ah = (const __nv_bfloat16*)(smemc + buf * STAGE_BYTES);
        const __nv_bfloat16* Al = Ah + 128 * LDK;
        const __nv_bfloat16* Bh = Al + 128 * LDK;
        const __nv_bfloat16* Bl = Bh + 128 * LDK;

        #pragma unroll
        for (int ks = 0; ks < 2; ks++) {
            wmma::fragment<wmma::matrix_a, 16, 16, 16, __nv_bfloat16, wmma::row_major> ah[2], al[2];
            wmma::fragment<wmma::matrix_b, 16, 16, 16, __nv_bfloat16, wmma::col_major> bh[4], bl[4];
            #pragma unroll
            for (int i = 0; i < 2; i++) {
                wmma::load_matrix_sync(ah[i], Ah + (wr * 32 + i * 16) * LDK + ks * 16, LDK);
                wmma::load_matrix_sync(al[i], Al + (wr * 32 + i * 16) * LDK + ks * 16, LDK);
            }
            #pragma unroll
            for (int j = 0; j < 4; j++) {
                wmma::load_matrix_sync(bh[j], Bh + (wc * 64 + j * 16) * LDK + ks * 16, LDK);
                wmma::load_matrix_sync(bl[j], Bl + (wc * 64 + j * 16) * LDK + ks * 16, LDK);
            }
            #pragma unroll
            for (int i = 0; i < 2; i++)
                #pragma unroll
                for (int j = 0; j < 4; j++) {
                    wmma::mma_sync(acc[i][j], ah[i], bh[j], acc[i][j]);
                    wmma::mma_sync(acc[i][j], ah[i], bl[j], acc[i][j]);
                    wmma::mma_sync(acc[i][j], al[i], bh[j], acc[i][j]);
                }
        }
        if (more) {
            __nv_bfloat16* base = (__nv_bfloat16*)(smemc + (buf ^ 1) * STAGE_BYTES);
            cvtstore16(pa, base,               base + 128 * LDK,     ra * LDK + ko);
            cvtstore16(pb, base + 2 * 128 * LDK, base + 3 * 128 * LDK, ra * LDK + ko);
            __syncthreads();
            buf ^= 1;
        }
    }

    // Dump accumulators to smem C (aliases stage memory — sync first).
    __syncthreads();
    float* Cs = (float*)smemc;
    #pragma unroll
    for (int i = 0; i < 2; i++)
        #pragma unroll
        for (int j = 0; j < 4; j++)
            wmma::store_matrix_sync(&Cs[(wr * 32 + i * 16) * CLD + wc * 64 + j * 16],
                                    acc[i][j], CLD, wmma::mem_row_major);
    __syncthreads();
}

// ---------------------------------------------------------------------------
// Kernel 1: QKV projection (tensor), epilogue: bias + RoPE, scatter (b,h,t,d).
// ---------------------------------------------------------------------------
__global__ __launch_bounds__(256) void qkv_gemm(
    const float* __restrict__ x,
    const float* __restrict__ Wq, const float* __restrict__ bq,
    const float* __restrict__ Wk, const float* __restrict__ bk,
    const float* __restrict__ Wv, const float* __restrict__ bv)
{
    extern __shared__ __align__(16) char smemc[];
    const int z = blockIdx.z;
    const float* W    = (z == 0) ? Wq : (z == 1) ? Wk : Wv;
    const float* bias = (z == 0) ? bq : (z == 1) ? bk : bv;
    float* out        = (z == 0) ? g_q : (z == 1) ? g_k : g_v;

    const int row0 = blockIdx.y * 128;
    const int col0 = blockIdx.x * 128;

    gemm_mainloop_to_smem(smemc, x, W, row0, col0);
    const float* Cs = (const float*)smemc;

    const int tid = threadIdx.x;
    const int tx = tid & 15, ty = tid >> 4;
    const int d0 = tx * 4;
    const int h0 = blockIdx.x * 2;

    float4 bb0 = *(const float4*)&bias[col0 + d0];
    float4 bb1 = *(const float4*)&bias[col0 + 64 + d0];
    float bvv[8] = {bb0.x, bb0.y, bb0.z, bb0.w, bb1.x, bb1.y, bb1.z, bb1.w};

    float th0 = 0.f, th1 = 0.f;
    if (z < 2) {
        th0 = expf(-((float)d0)       * (LN1E4 / 64.0f));
        th1 = expf(-((float)(d0 + 2)) * (LN1E4 / 64.0f));
    }

    #pragma unroll
    for (int r8 = 0; r8 < 8; r8++) {
        int rl = ty * 8 + r8;
        int row = row0 + rl;
        int b = row >> 11;
        int t = row & 2047;
        float4 c0 = *(const float4*)&Cs[rl * CLD + d0];
        float4 c1 = *(const float4*)&Cs[rl * CLD + 64 + d0];
        float v[8] = {c0.x + bvv[0], c0.y + bvv[1], c0.z + bvv[2], c0.w + bvv[3],
                      c1.x + bvv[4], c1.y + bvv[5], c1.z + bvv[6], c1.w + bvv[7]};
        if (z < 2) {
            float cc0, ss0, cc1, ss1;
            sincosf((float)t * th0, &ss0, &cc0);
            sincosf((float)t * th1, &ss1, &cc1);
            float r0 = v[0] * cc0 - v[1] * ss0, r1 = v[0] * ss0 + v[1] * cc0;
            float r2 = v[2] * cc1 - v[3] * ss1, r3 = v[2] * ss1 + v[3] * cc1;
            float r4 = v[4] * cc0 - v[5] * ss0, r5 = v[4] * ss0 + v[5] * cc0;
            float r6 = v[6] * cc1 - v[7] * ss1, r7 = v[6] * ss1 + v[7] * cc1;
            v[0] = r0; v[1] = r1; v[2] = r2; v[3] = r3;
            v[4] = r4; v[5] = r5; v[6] = r6; v[7] = r7;
        }
        float4 o0 = {v[0], v[1], v[2], v[3]};
        float4 o1 = {v[4], v[5], v[6], v[7]};
        *(float4*)&out[(((size_t)b * NH + h0) * TSEQ + t) * HS + d0] = o0;
        *(float4*)&out[(((size_t)b * NH + h0 + 1) * TSEQ + t) * HS + d0] = o1;
    }
}

// ---------------------------------------------------------------------------
// Kernel 2: flash attention (fp32/FFMA2, causal), no-max softmax.
// Br=128, Bc=64. 256 threads, 8q x 4k microtile, plain smem (no dup).
// ---------------------------------------------------------------------------
#define ATTN_SMEM ((64 * QSTR * 2 + 64 * KSTR * 2) * 4)   // 102400 bytes

__global__ __launch_bounds__(256) void attn_kernel()
{
    extern __shared__ __align__(16) float sm[];
    float* Qs = sm;                  // [d][q]  64 x 132, pre-scaled
    float* Ks = Qs + 64 * QSTR;      // [d][k]  64 x 68
    float* Ps = Ks + 64 * KSTR;      // [k][q]  64 x 132
    float* Vs = Ps + 64 * QSTR;      // [k][d]  64 x 68

    const int tid = threadIdx.x;
    const int tx = tid & 15, ty = tid >> 4;
    const int qt = (gridDim.x - 1) - blockIdx.x;    // heavy tiles first
    const int bh = blockIdx.y;

    const float* qp = g_q + (size_t)bh * TSEQ * HS;
    const float* kp = g_k + (size_t)bh * TSEQ * HS;
    const float* vp = g_v + (size_t)bh * TSEQ * HS;

    const int q0 = qt * 128;

    // Load Q tile transposed, pre-scaled by 1/sqrt(hs)
    #pragma unroll
    for (int jj = 0; jj < 8; jj++) {
        int idx = tid + jj * 256;
        int r = idx >> 4;
        int c4 = (idx & 15) * 4;
        float4 qv = *(const float4*)&qp[(size_t)(q0 + r) * HS + c4];
        Qs[(c4 + 0) * QSTR + r] = qv.x * 0.125f;
        Qs[(c4 + 1) * QSTR + r] = qv.y * 0.125f;
        Qs[(c4 + 2) * QSTR + r] = qv.z * 0.125f;
        Qs[(c4 + 3) * QSTR + r] = qv.w * 0.125f;
    }

    // Stage K/V tile 0
    float4 kreg[4], vreg[4];
    #pragma unroll
    for (int jj = 0; jj < 4; jj++) {
        int idx = tid + jj * 256;
        int r = idx >> 4;
        int c4 = (idx & 15) * 4;
        kreg[jj] = *(const float4*)&kp[(size_t)r * HS + c4];
        vreg[jj] = *(const float4*)&vp[(size_t)r * HS + c4];
    }
    #pragma unroll
    for (int jj = 0; jj < 4; jj++) {
        int idx = tid + jj * 256;
        int r = idx >> 4;
        int c4 = (idx & 15) * 4;
        Ks[(c4 + 0) * KSTR + r] = kreg[jj].x;
        Ks[(c4 + 1) * KSTR + r] = kreg[jj].y;
        Ks[(c4 + 2) * KSTR + r] = kreg[jj].z;
        Ks[(c4 + 3) * KSTR + r] = kreg[jj].w;
        *(float4*)&Vs[r * KSTR + c4] = vreg[jj];
    }

    u64 O[4][4];                     // [q-row-pair][d-col], packed f32x2
    u64 l2[4];                       // packed per-lane partial row sums
    #pragma unroll
    for (int p = 0; p < 4; p++) {
        l2[p] = 0ULL;
        #pragma unroll
        for (int j = 0; j < 4; j++) O[p][j] = 0ULL;
    }

    const int ktmax = 2 * qt + 1;
    __syncthreads();

    for (int kt = 0; kt <= ktmax; kt++) {
        // S = (Q/8) K^T, packed over q-row pairs
        u64 s2[4][4];
        #pragma unroll
        for (int p = 0; p < 4; p++)
            #pragma unroll
            for (int j = 0; j < 4; j++) s2[p][j] = 0ULL;
        #pragma unroll 8
        for (int d = 0; d < 64; d++) {
            const float* qb = &Qs[d * QSTR + ty * 4];
            ulonglong2 aA = *(const ulonglong2*)qb;
            ulonglong2 aB = *(const ulonglong2*)(qb + 64);
            float4 kv = *(const float4*)&Ks[d * KSTR + tx * 4];
            u64 aa[4] = {aA.x, aA.y, aB.x, aB.y};
            u64 bb[4] = {bc2(kv.x), bc2(kv.y), bc2(kv.z), bc2(kv.w)};
            #pragma unroll
            for (int p = 0; p < 4; p++)
                #pragma unroll
                for (int j = 0; j < 4; j++)
                    fma2(s2[p][j], aa[p], bb[j]);
        }

        // Prefetch next K/V tile into registers (hidden under exp + PV)
        if (kt < ktmax) {
            const int kn = (kt + 1) * 64;
            #pragma unroll
            for (int jj = 0; jj < 4; jj++) {
                int idx = tid + jj * 256;
                int r = idx >> 4;
                int c4 = (idx & 15) * 4;
                kreg[jj] = *(const float4*)&kp[(size_t)(kn + r) * HS + c4];
                vreg[jj] = *(const float4*)&vp[(size_t)(kn + r) * HS + c4];
            }
        }

        // exp (no max subtraction), causal mask, l accumulate, store P
        const int k0 = kt * 64;
        const bool diag = (kt >= 2 * qt);
        #pragma unroll
        for (int p = 0; p < 4; p++) {
            float2 f[4];
            #pragma unroll
            for (int j = 0; j < 4; j++) f[j] = up2(s2[p][j]);
            const int rb = ((p >> 1) << 6) + ty * 4 + ((p & 1) << 1);
            if (diag) {
                const int r0 = q0 + rb, r1 = r0 + 1;
                #pragma unroll
                for (int j = 0; j < 4; j++) {
                    int c = k0 + tx * 4 + j;
                    if (c > r0) f[j].x = -1e30f;
                    if (c > r1) f[j].y = -1e30f;
                }
            }
            #pragma unroll
            for (int j = 0; j < 4; j++) {
                u64 pe = pk2(__expf(f[j].x), __expf(f[j].y));
                add2(l2[p], pe);
                *(u64*)&Ps[(tx * 4 + j) * QSTR + rb] = pe;
            }
        }
        __syncthreads();             // Ps visible; everyone done with Ks

        // O += P V
        #pragma unroll 8
        for (int kk = 0; kk < 64; kk++) {
            const float* pb = &Ps[kk * QSTR + ty * 4];
            ulonglong2 aA = *(const ulonglong2*)pb;
            ulonglong2 aB = *(const ulonglong2*)(pb + 64);
            float4 vv = *(const float4*)&Vs[kk * KSTR + tx * 4];
            u64 aa[4] = {aA.x, aA.y, aB.x, aB.y};
            u64 bb[4] = {bc2(vv.x), bc2(vv.y), bc2(vv.z), bc2(vv.w)};
            #pragma unroll
            for (int p = 0; p < 4; p++)
                #pragma unroll
                for (int j = 0; j < 4; j++)
                    fma2(O[p][j], aa[p], bb[j]);
        }
        __syncthreads();             // Vs/Ps reads done

        if (kt < ktmax) {            // stage next tile
            #pragma unroll
            for (int jj = 0; jj < 4; jj++) {
                int idx = tid + jj * 256;
                int r = idx >> 4;
                int c4 = (idx & 15) * 4;
                Ks[(c4 + 0) * KSTR + r] = kreg[jj].x;
                Ks[(c4 + 1) * KSTR + r] = kreg[jj].y;
                Ks[(c4 + 2) * KSTR + r] = kreg[jj].z;
                Ks[(c4 + 3) * KSTR + r] = kreg[jj].w;
                *(float4*)&Vs[r * KSTR + c4] = vreg[jj];
            }
            __syncthreads();         // staging visible for next S
        }
    }

    // Final l reduction across the 16 tx lanes (once)
    float l[8];
    #pragma unroll
    for (int p = 0; p < 4; p++) {
        float2 f = up2(l2[p]);
        l[2 * p] = f.x;
        l[2 * p + 1] = f.y;
    }
    #pragma unroll
    for (int i = 0; i < 8; i++)
        #pragma unroll
        for (int off = 8; off >= 1; off >>= 1)
            l[i] += __shfl_xor_sync(0xffffffffu, l[i], off);

    // Normalize, write y in (b, t, c) layout for the output projection
    const int b = bh >> 4, h = bh & 15;
    #pragma unroll
    for (int p = 0; p < 4; p++) {
        float2 f0 = up2(O[p][0]);
        float2 f1 = up2(O[p][1]);
        float2 f2 = up2(O[p][2]);
        float2 f3 = up2(O[p][3]);
        int i0 = 2 * p;
        float inv0 = 1.0f / l[i0];
        float inv1 = 1.0f / l[i0 + 1];
        int t0 = q0 + ((i0 >> 2) << 6) + ty * 4 + (i0 & 3);
        float4 o0 = {f0.x * inv0, f1.x * inv0, f2.x * inv0, f3.x * inv0};
        float4 o1 = {f0.y * inv1, f1.y * inv1, f2.y * inv1, f3.y * inv1};
        *(float4*)&g_y[((size_t)b * TSEQ + t0) * CEMB + h * HS + tx * 4] = o0;
        *(float4*)&g_y[((size_t)b * TSEQ + t0 + 1) * CEMB + h * HS + tx * 4] = o1;
    }
}

// ---------------------------------------------------------------------------
// Kernel 3: output projection (tensor), plain bias epilogue.
// ---------------------------------------------------------------------------
__global__ __launch_bounds__(256) void proj_gemm(
    const float* __restrict__ Wp, const float* __restrict__ bp,
    float* __restrict__ out)
{
    extern __shared__ __align__(16) char smemc[];
    const int row0 = blockIdx.y * 128;
    const int col0 = blockIdx.x * 128;

    gemm_mainloop_to_smem(smemc, g_y, Wp, row0, col0);
    const float* Cs = (const float*)smemc;

    const int tid = threadIdx.x;
    const int tx = tid & 15, ty = tid >> 4;

    float4 bb0 = *(const float4*)&bp[col0 + tx * 4];
    float4 bb1 = *(const float4*)&bp[col0 + 64 + tx * 4];

    #pragma unroll
    for (int r8 = 0; r8 < 8; r8++) {
        int rl = ty * 8 + r8;
        size_t row = (size_t)(row0 + rl);
        float4 c0 = *(const float4*)&Cs[rl * CLD + tx * 4];
        float4 c1 = *(const float4*)&Cs[rl * CLD + 64 + tx * 4];
        float4 o0 = {c0.x + bb0.x, c0.y + bb0.y, c0.z + bb0.z, c0.w + bb0.w};
        float4 o1 = {c1.x + bb1.x, c1.y + bb1.y, c1.z + bb1.z, c1.w + bb1.w};
        *(float4*)&out[row * CEMB + col0 + tx * 4] = o0;
        *(float4*)&out[row * CEMB + col0 + 64 + tx * 4] = o1;
    }
}

// ---------------------------------------------------------------------------
extern "C" void kernel_launch(void* const* d_in, const int* in_sizes, int n_in,
                              void* d_out, int out_size)
{
    const float* x  = (const float*)d_in[0];
    const float* Wq = (const float*)d_in[1];
    const float* bq = (const float*)d_in[2];
    const float* Wk = (const float*)d_in[3];
    const float* bk = (const float*)d_in[4];
    const float* Wv = (const float*)d_in[5];
    const float* bv = (const float*)d_in[6];
    const float* Wp = (const float*)d_in[7];
    const float* bp = (const float*)d_in[8];
    float* out = (float*)d_out;

    cudaFuncSetAttribute(qkv_gemm,
                         cudaFuncAttributeMaxDynamicSharedMemorySize, GSMEM);
    cudaFuncSetAttribute(proj_gemm,
                         cudaFuncAttributeMaxDynamicSharedMemorySize, GSMEM);
    cudaFuncSetAttribute(attn_kernel,
                         cudaFuncAttributeMaxDynamicSharedMemorySize, ATTN_SMEM);

    qkv_gemm<<<dim3(CEMB / 128, BROWS / 128, 3), 256, GSMEM>>>(
        x, Wq, bq, Wk, bk, Wv, bv);
    attn_kernel<<<dim3(TSEQ / 128, 2 * NH), 256, ATTN_SMEM>>>();
    proj_gemm<<<dim3(CEMB / 128, BROWS / 128), 256, GSMEM>>>(Wp, bp, out);
}

// round 14
// speedup vs baseline: 2.1081x; 1.3998x over previous
#include <cuda_runtime.h>
#include <cuda_bf16.h>
#include <mma.h>
#include <math.h>

using namespace nvcuda;

// ---------------------------------------------------------------------------
// CausalSelfAttention: x -> (QKV proj + RoPE) -> flash attention -> out proj
// B=2, T=2048, C=1024, nh=16, hs=64.
// R14: ALL GEMMs on tensor cores (wmma bf16, 2-term split, 3 mma passes).
// Attention: no-max softmax => O stays in wmma accumulators across all
// k-tiles (no rescale); S -> smem -> exp -> split-bf16 P -> PV mma.
// ---------------------------------------------------------------------------

#define NH     16
#define HS     64
#define TSEQ   2048
#define CEMB   1024
#define BROWS  4096
#define LN1E4  9.210340371976184f
#define LDK    40             // GEMM stage tiles leading dim (bf16)
#define CLD    132            // GEMM epilogue C smem row stride (floats)

// GEMM smem: 2 stages x (Ahi|Alo|Bhi|Blo), each 128*LDK bf16 = 10240 B
#define STAGE_BYTES  (4 * 128 * LDK * 2)          // 40960
#define GSMEM        (2 * STAGE_BYTES)            // 81920 (>= C: 128*CLD*4)

// ---- attention smem layout (bytes) ----------------------------------------
#define QLD    72             // Q/P bf16 leading dim
#define KLD    72             // K/V bf16 leading dim
#define SLD    68             // S fp32 leading dim
#define AQ_H   0                                  // 128*QLD*2 = 18432
#define AQ_L   (AQ_H + 128 * QLD * 2)             // 18432
#define AKV0   (AQ_L + 128 * QLD * 2)             // 36864; per-buf 4x(64*KLD*2)
#define AKVSZ  (4 * 64 * KLD * 2)                 // 36864
#define ASS    (AKV0 + 2 * AKVSZ)                 // 110592; 128*SLD*4 = 34816
#define APH    (ASS + 128 * SLD * 4)              // 145408
#define APL    (APH + 128 * QLD * 2)              // 163840
#define ALS    (APL + 128 * QLD * 2)              // 182272; 128*4
#define ATTN_SMEM (ALS + 512)                     // 182784

typedef unsigned long long u64;

// pack two floats to bf16x2 (x0 -> low half / first element in memory)
__device__ __forceinline__ unsigned cvt2(float x0, float x1) {
    unsigned u;
    asm("cvt.rn.bf16x2.f32 %0, %1, %2;" : "=r"(u) : "f"(x1), "f"(x0));
    return u;
}

// Scratch (allocation-free): Q/K/V in (b,h,t,d) layout, y in (b,t,c) layout.
__device__ __align__(16) float g_q[2 * NH * TSEQ * HS];
__device__ __align__(16) float g_k[2 * NH * TSEQ * HS];
__device__ __align__(16) float g_v[2 * NH * TSEQ * HS];
__device__ __align__(16) float g_y[2 * TSEQ * CEMB];

// Convert 16 fp32 -> split bf16 (hi, lo), store 32B each to smem.
__device__ __forceinline__ void cvtstore16(const float4* v,
                                           __nv_bfloat16* H, __nv_bfloat16* L,
                                           int off)
{
    unsigned uh[8], ul[8];
    #pragma unroll
    for (int q = 0; q < 4; q++) {
        float a = v[q].x, b = v[q].y, c = v[q].z, d = v[q].w;
        unsigned h0 = cvt2(a, b), h1 = cvt2(c, d);
        uh[2 * q] = h0; uh[2 * q + 1] = h1;
        float r0 = a - __uint_as_float(h0 << 16);
        float r1 = b - __uint_as_float(h0 & 0xffff0000u);
        float r2 = c - __uint_as_float(h1 << 16);
        float r3 = d - __uint_as_float(h1 & 0xffff0000u);
        ul[2 * q] = cvt2(r0, r1); ul[2 * q + 1] = cvt2(r2, r3);
    }
    *(uint4*)(H + off)     = make_uint4(uh[0], uh[1], uh[2], uh[3]);
    *(uint4*)(H + off + 8) = make_uint4(uh[4], uh[5], uh[6], uh[7]);
    *(uint4*)(L + off)     = make_uint4(ul[0], ul[1], ul[2], ul[3]);
    *(uint4*)(L + off + 8) = make_uint4(ul[4], ul[5], ul[6], ul[7]);
}

// ---------------------------------------------------------------------------
// Split-bf16 wmma mainloop (shared by both projections). Unchanged from R13.
// ---------------------------------------------------------------------------
__device__ __forceinline__ void gemm_mainloop_to_smem(
    char* smemc, const float* __restrict__ Ag, const float* __restrict__ Bg,
    int row0, int col0)
{
    const int tid = threadIdx.x;
    const int wid = tid >> 5;
    const int wr = wid >> 1;
    const int wc = wid & 1;

    const int ra = tid >> 1;
    const int ko = (tid & 1) * 16;

    const float* apg = Ag + (size_t)(row0 + ra) * CEMB + ko;
    const float* bpg = Bg + (size_t)(col0 + ra) * CEMB + ko;

    wmma::fragment<wmma::accumulator, 16, 16, 16, float> acc[2][4];
    #pragma unroll
    for (int i = 0; i < 2; i++)
        #pragma unroll
        for (int j = 0; j < 4; j++) wmma::fill_fragment(acc[i][j], 0.0f);

    float4 pa[4], pb[4];
    #pragma unroll
    for (int q = 0; q < 4; q++) {
        pa[q] = *(const float4*)(apg + 4 * q);
        pb[q] = *(const float4*)(bpg + 4 * q);
    }
    {
        __nv_bfloat16* base = (__nv_bfloat16*)smemc;
        cvtstore16(pa, base,               base + 128 * LDK,     ra * LDK + ko);
        cvtstore16(pb, base + 2 * 128 * LDK, base + 3 * 128 * LDK, ra * LDK + ko);
    }
    __syncthreads();

    int buf = 0;
    #pragma unroll 1
    for (int kc = 0; kc < CEMB; kc += 32) {
        const bool more = (kc + 32 < CEMB);
        if (more) {
            #pragma unroll
            for (int q = 0; q < 4; q++) {
                pa[q] = *(const float4*)(apg + kc + 32 + 4 * q);
                pb[q] = *(const float4*)(bpg + kc + 32 + 4 * q);
            }
        }
        const __nv_bfloat16* Ah = (const __nv_bfloat16*)(smemc + buf * STAGE_BYTES);
        const __nv_bfloat16* Al = Ah + 128 * LDK;
        const __nv_bfloat16* Bh = Al + 128 * LDK;
        const __nv_bfloat16* Bl = Bh + 128 * LDK;

        #pragma unroll
        for (int ks = 0; ks < 2; ks++) {
            wmma::fragment<wmma::matrix_a, 16, 16, 16, __nv_bfloat16, wmma::row_major> ah[2], al[2];
            wmma::fragment<wmma::matrix_b, 16, 16, 16, __nv_bfloat16, wmma::col_major> bh[4], bl[4];
            #pragma unroll
            for (int i = 0; i < 2; i++) {
                wmma::load_matrix_sync(ah[i], Ah + (wr * 32 + i * 16) * LDK + ks * 16, LDK);
                wmma::load_matrix_sync(al[i], Al + (wr * 32 + i * 16) * LDK + ks * 16, LDK);
            }
            #pragma unroll
            for (int j = 0; j < 4; j++) {
                wmma::load_matrix_sync(bh[j], Bh + (wc * 64 + j * 16) * LDK + ks * 16, LDK);
                wmma::load_matrix_sync(bl[j], Bl + (wc * 64 + j * 16) * LDK + ks * 16, LDK);
            }
            #pragma unroll
            for (int i = 0; i < 2; i++)
                #pragma unroll
                for (int j = 0; j < 4; j++) {
                    wmma::mma_sync(acc[i][j], ah[i], bh[j], acc[i][j]);
                    wmma::mma_sync(acc[i][j], ah[i], bl[j], acc[i][j]);
                    wmma::mma_sync(acc[i][j], al[i], bh[j], acc[i][j]);
                }
        }
        if (more) {
            __nv_bfloat16* base = (__nv_bfloat16*)(smemc + (buf ^ 1) * STAGE_BYTES);
            cvtstore16(pa, base,               base + 128 * LDK,     ra * LDK + ko);
            cvtstore16(pb, base + 2 * 128 * LDK, base + 3 * 128 * LDK, ra * LDK + ko);
            __syncthreads();
            buf ^= 1;
        }
    }

    __syncthreads();
    float* Cs = (float*)smemc;
    #pragma unroll
    for (int i = 0; i < 2; i++)
        #pragma unroll
        for (int j = 0; j < 4; j++)
            wmma::store_matrix_sync(&Cs[(wr * 32 + i * 16) * CLD + wc * 64 + j * 16],
                                    acc[i][j], CLD, wmma::mem_row_major);
    __syncthreads();
}

// ---------------------------------------------------------------------------
// Kernel 1: QKV projection (tensor), epilogue: bias + RoPE, scatter (b,h,t,d).
// ---------------------------------------------------------------------------
__global__ __launch_bounds__(256) void qkv_gemm(
    const float* __restrict__ x,
    const float* __restrict__ Wq, const float* __restrict__ bq,
    const float* __restrict__ Wk, const float* __restrict__ bk,
    const float* __restrict__ Wv, const float* __restrict__ bv)
{
    extern __shared__ __align__(16) char smemc[];
    const int z = blockIdx.z;
    const float* W    = (z == 0) ? Wq : (z == 1) ? Wk : Wv;
    const float* bias = (z == 0) ? bq : (z == 1) ? bk : bv;
    float* out        = (z == 0) ? g_q : (z == 1) ? g_k : g_v;

    const int row0 = blockIdx.y * 128;
    const int col0 = blockIdx.x * 128;

    gemm_mainloop_to_smem(smemc, x, W, row0, col0);
    const float* Cs = (const float*)smemc;

    const int tid = threadIdx.x;
    const int tx = tid & 15, ty = tid >> 4;
    const int d0 = tx * 4;
    const int h0 = blockIdx.x * 2;

    float4 bb0 = *(const float4*)&bias[col0 + d0];
    float4 bb1 = *(const float4*)&bias[col0 + 64 + d0];
    float bvv[8] = {bb0.x, bb0.y, bb0.z, bb0.w, bb1.x, bb1.y, bb1.z, bb1.w};

    float th0 = 0.f, th1 = 0.f;
    if (z < 2) {
        th0 = expf(-((float)d0)       * (LN1E4 / 64.0f));
        th1 = expf(-((float)(d0 + 2)) * (LN1E4 / 64.0f));
    }

    #pragma unroll
    for (int r8 = 0; r8 < 8; r8++) {
        int rl = ty * 8 + r8;
        int row = row0 + rl;
        int b = row >> 11;
        int t = row & 2047;
        float4 c0 = *(const float4*)&Cs[rl * CLD + d0];
        float4 c1 = *(const float4*)&Cs[rl * CLD + 64 + d0];
        float v[8] = {c0.x + bvv[0], c0.y + bvv[1], c0.z + bvv[2], c0.w + bvv[3],
                      c1.x + bvv[4], c1.y + bvv[5], c1.z + bvv[6], c1.w + bvv[7]};
        if (z < 2) {
            float cc0, ss0, cc1, ss1;
            sincosf((float)t * th0, &ss0, &cc0);
            sincosf((float)t * th1, &ss1, &cc1);
            float r0 = v[0] * cc0 - v[1] * ss0, r1 = v[0] * ss0 + v[1] * cc0;
            float r2 = v[2] * cc1 - v[3] * ss1, r3 = v[2] * ss1 + v[3] * cc1;
            float r4 = v[4] * cc0 - v[5] * ss0, r5 = v[4] * ss0 + v[5] * cc0;
            float r6 = v[6] * cc1 - v[7] * ss1, r7 = v[6] * ss1 + v[7] * cc1;
            v[0] = r0; v[1] = r1; v[2] = r2; v[3] = r3;
            v[4] = r4; v[5] = r5; v[6] = r6; v[7] = r7;
        }
        float4 o0 = {v[0], v[1], v[2], v[3]};
        float4 o1 = {v[4], v[5], v[6], v[7]};
        *(float4*)&out[(((size_t)b * NH + h0) * TSEQ + t) * HS + d0] = o0;
        *(float4*)&out[(((size_t)b * NH + h0 + 1) * TSEQ + t) * HS + d0] = o1;
    }
}

// ---------------------------------------------------------------------------
// Kernel 2: flash attention on tensor cores (split-bf16 wmma, causal),
// no-max softmax: O accumulates in wmma fragments across all k-tiles.
// Br=128, Bc=64, 256 threads (8 warps as 4x2).
// ---------------------------------------------------------------------------
__global__ __launch_bounds__(256) void attn_kernel()
{
    extern __shared__ __align__(16) char smc[];
    __nv_bfloat16* QH = (__nv_bfloat16*)(smc + AQ_H);
    __nv_bfloat16* QL = (__nv_bfloat16*)(smc + AQ_L);
    float*         SS = (float*)(smc + ASS);
    __nv_bfloat16* PH = (__nv_bfloat16*)(smc + APH);
    __nv_bfloat16* PL = (__nv_bfloat16*)(smc + APL);
    float*         Ls = (float*)(smc + ALS);

    const int tid = threadIdx.x;
    const int wid = tid >> 5;
    const int wr = wid >> 1;            // warp row group (32 q-rows)
    const int wc = wid & 1;             // warp col group (32 keys / 32 dims)
    const int qt = (gridDim.x - 1) - blockIdx.x;    // heavy tiles first
    const int bh = blockIdx.y;

    const float* qp = g_q + (size_t)bh * TSEQ * HS;
    const float* kp = g_k + (size_t)bh * TSEQ * HS;
    const float* vp = g_v + (size_t)bh * TSEQ * HS;

    const int q0 = qt * 128;

    // Split-convert Q (pre-scaled by 1/8) into QH/QL
    {
        const int r = tid >> 1;
        const int c0 = (tid & 1) * 32;
        #pragma unroll
        for (int h = 0; h < 2; h++) {
            float4 v[4];
            #pragma unroll
            for (int q = 0; q < 4; q++) {
                float4 t = *(const float4*)&qp[(size_t)(q0 + r) * HS + c0 + 16 * h + 4 * q];
                v[q] = make_float4(t.x * 0.125f, t.y * 0.125f,
                                   t.z * 0.125f, t.w * 0.125f);
            }
            cvtstore16(v, QH, QL, r * QLD + c0 + 16 * h);
        }
    }

    // K/V staging state
    const int kr = tid >> 2;            // 0..63
    const int ko = (tid & 3) * 16;
    float4 kreg[4], vreg[4];
    #pragma unroll
    for (int q = 0; q < 4; q++) {
        kreg[q] = *(const float4*)&kp[(size_t)kr * HS + ko + 4 * q];
        vreg[q] = *(const float4*)&vp[(size_t)kr * HS + ko + 4 * q];
    }
    {
        __nv_bfloat16* base = (__nv_bfloat16*)(smc + AKV0);
        cvtstore16(kreg, base,                base + 64 * KLD,     kr * KLD + ko);
        cvtstore16(vreg, base + 2 * 64 * KLD, base + 3 * 64 * KLD, kr * KLD + ko);
    }

    wmma::fragment<wmma::accumulator, 16, 16, 16, float> of[2][2];
    #pragma unroll
    for (int i = 0; i < 2; i++)
        #pragma unroll
        for (int j = 0; j < 2; j++) wmma::fill_fragment(of[i][j], 0.0f);
    float lpart = 0.0f;

    const int er = tid >> 1;            // exp-stage row (0..127)
    const int ec = (tid & 1) * 32;      // exp-stage col base
    const int ktmax = 2 * qt + 1;
    int buf = 0;
    __syncthreads();

    #pragma unroll 1
    for (int kt = 0; kt <= ktmax; kt++) {
        const __nv_bfloat16* KH = (const __nv_bfloat16*)(smc + AKV0 + buf * AKVSZ);
        const __nv_bfloat16* KL = KH + 64 * KLD;
        const __nv_bfloat16* VH = KL + 64 * KLD;
        const __nv_bfloat16* VL = VH + 64 * KLD;

        // ---- S = (Q/8) K^T  (split, 3 passes) ----
        wmma::fragment<wmma::accumulator, 16, 16, 16, float> sacc[2][2];
        #pragma unroll
        for (int i = 0; i < 2; i++)
            #pragma unroll
            for (int j = 0; j < 2; j++) wmma::fill_fragment(sacc[i][j], 0.0f);
        #pragma unroll
        for (int ds = 0; ds < 4; ds++) {
            wmma::fragment<wmma::matrix_a, 16, 16, 16, __nv_bfloat16, wmma::row_major> ah[2], al[2];
            wmma::fragment<wmma::matrix_b, 16, 16, 16, __nv_bfloat16, wmma::col_major> bh[2], bl[2];
            #pragma unroll
            for (int i = 0; i < 2; i++) {
                wmma::load_matrix_sync(ah[i], QH + (wr * 32 + i * 16) * QLD + ds * 16, QLD);
                wmma::load_matrix_sync(al[i], QL + (wr * 32 + i * 16) * QLD + ds * 16, QLD);
            }
            #pragma unroll
            for (int j = 0; j < 2; j++) {
                wmma::load_matrix_sync(bh[j], KH + (wc * 32 + j * 16) * KLD + ds * 16, KLD);
                wmma::load_matrix_sync(bl[j], KL + (wc * 32 + j * 16) * KLD + ds * 16, KLD);
            }
            #pragma unroll
            for (int i = 0; i < 2; i++)
                #pragma unroll
                for (int j = 0; j < 2; j++) {
                    wmma::mma_sync(sacc[i][j], ah[i], bh[j], sacc[i][j]);
                    wmma::mma_sync(sacc[i][j], ah[i], bl[j], sacc[i][j]);
                    wmma::mma_sync(sacc[i][j], al[i], bh[j], sacc[i][j]);
                }
        }

        // Prefetch next K/V tile (hidden under exp + PV)
        if (kt < ktmax) {
            const int kn = (kt + 1) * 64;
            #pragma unroll
            for (int q = 0; q < 4; q++) {
                kreg[q] = *(const float4*)&kp[(size_t)(kn + kr) * HS + ko + 4 * q];
                vreg[q] = *(const float4*)&vp[(size_t)(kn + kr) * HS + ko + 4 * q];
            }
        }

        #pragma unroll
        for (int i = 0; i < 2; i++)
            #pragma unroll
            for (int j = 0; j < 2; j++)
                wmma::store_matrix_sync(&SS[(wr * 32 + i * 16) * SLD + wc * 32 + j * 16],
                                        sacc[i][j], SLD, wmma::mem_row_major);
        __syncthreads();

        // ---- exp (no max), causal mask, l accumulate, split-convert P ----
        {
            const int k0 = kt * 64;
            const bool diag = (kt >= 2 * qt);
            const int gr = q0 + er;
            float e[32];
            #pragma unroll
            for (int q = 0; q < 8; q++) {
                float4 s4 = *(const float4*)&SS[er * SLD + ec + 4 * q];
                float s[4] = {s4.x, s4.y, s4.z, s4.w};
                #pragma unroll
                for (int m = 0; m < 4; m++) {
                    int jj = 4 * q + m;
                    bool ok = !diag || (k0 + ec + jj <= gr);
                    float ev = ok ? __expf(s[m]) : 0.0f;
                    e[jj] = ev;
                    lpart += ev;
                }
            }
            #pragma unroll
            for (int h = 0; h < 2; h++) {
                float4 v[4];
                #pragma unroll
                for (int q = 0; q < 4; q++)
                    v[q] = make_float4(e[16 * h + 4 * q], e[16 * h + 4 * q + 1],
                                       e[16 * h + 4 * q + 2], e[16 * h + 4 * q + 3]);
                cvtstore16(v, PH, PL, er * QLD + ec + 16 * h);
            }
        }
        __syncthreads();

        // ---- O += P V  (split, 3 passes) ----
        #pragma unroll
        for (int ks = 0; ks < 4; ks++) {
            wmma::fragment<wmma::matrix_a, 16, 16, 16, __nv_bfloat16, wmma::row_major> ph[2], pl[2];
            wmma::fragment<wmma::matrix_b, 16, 16, 16, __nv_bfloat16, wmma::row_major> vh[2], vl[2];
            #pragma unroll
            for (int i = 0; i < 2; i++) {
                wmma::load_matrix_sync(ph[i], PH + (wr * 32 + i * 16) * QLD + ks * 16, QLD);
                wmma::load_matrix_sync(pl[i], PL + (wr * 32 + i * 16) * QLD + ks * 16, QLD);
            }
            #pragma unroll
            for (int j = 0; j < 2; j++) {
                wmma::load_matrix_sync(vh[j], VH + (ks * 16) * KLD + wc * 32 + j * 16, KLD);
                wmma::load_matrix_sync(vl[j], VL + (ks * 16) * KLD + wc * 32 + j * 16, KLD);
            }
            #pragma unroll
            for (int i = 0; i < 2; i++)
                #pragma unroll
                for (int j = 0; j < 2; j++) {
                    wmma::mma_sync(of[i][j], ph[i], vh[j], of[i][j]);
                    wmma::mma_sync(of[i][j], ph[i], vl[j], of[i][j]);
                    wmma::mma_sync(of[i][j], pl[i], vh[j], of[i][j]);
                }
        }
        __syncthreads();                 // K/V buf reads done (S & PV)

        if (kt < ktmax) {                // stage next K/V into other buffer
            __nv_bfloat16* base = (__nv_bfloat16*)(smc + AKV0 + (buf ^ 1) * AKVSZ);
            cvtstore16(kreg, base,                base + 64 * KLD,     kr * KLD + ko);
            cvtstore16(vreg, base + 2 * 64 * KLD, base + 3 * 64 * KLD, kr * KLD + ko);
            __syncthreads();
            buf ^= 1;
        }
    }

    // ---- epilogue: O frags -> SS, l -> Ls, normalize, write y ----
    #pragma unroll
    for (int i = 0; i < 2; i++)
        #pragma unroll
        for (int j = 0; j < 2; j++)
            wmma::store_matrix_sync(&SS[(wr * 32 + i * 16) * SLD + wc * 32 + j * 16],
                                    of[i][j], SLD, wmma::mem_row_major);
    {
        float lr = lpart + __shfl_xor_sync(0xffffffffu, lpart, 1);
        if ((tid & 1) == 0) Ls[er] = lr;
    }
    __syncthreads();

    {
        const int b = bh >> 4, h = bh & 15;
        const float inv = 1.0f / Ls[er];
        float* yrow = &g_y[((size_t)b * TSEQ + q0 + er) * CEMB + h * HS + ec];
        #pragma unroll
        for (int q = 0; q < 8; q++) {
            float4 o = *(const float4*)&SS[er * SLD + ec + 4 * q];
            float4 w = {o.x * inv, o.y * inv, o.z * inv, o.w * inv};
            *(float4*)&yrow[4 * q] = w;
        }
    }
}

// ---------------------------------------------------------------------------
// Kernel 3: output projection (tensor), plain bias epilogue.
// ---------------------------------------------------------------------------
__global__ __launch_bounds__(256) void proj_gemm(
    const float* __restrict__ Wp, const float* __restrict__ bp,
    float* __restrict__ out)
{
    extern __shared__ __align__(16) char smemc[];
    const int row0 = blockIdx.y * 128;
    const int col0 = blockIdx.x * 128;

    gemm_mainloop_to_smem(smemc, g_y, Wp, row0, col0);
    const float* Cs = (const float*)smemc;

    const int tid = threadIdx.x;
    const int tx = tid & 15, ty = tid >> 4;

    float4 bb0 = *(const float4*)&bp[col0 + tx * 4];
    float4 bb1 = *(const float4*)&bp[col0 + 64 + tx * 4];

    #pragma unroll
    for (int r8 = 0; r8 < 8; r8++) {
        int rl = ty * 8 + r8;
        size_t row = (size_t)(row0 + rl);
        float4 c0 = *(const float4*)&Cs[rl * CLD + tx * 4];
        float4 c1 = *(const float4*)&Cs[rl * CLD + 64 + tx * 4];
        float4 o0 = {c0.x + bb0.x, c0.y + bb0.y, c0.z + bb0.z, c0.w + bb0.w};
        float4 o1 = {c1.x + bb1.x, c1.y + bb1.y, c1.z + bb1.z, c1.w + bb1.w};
        *(float4*)&out[row * CEMB + col0 + tx * 4] = o0;
        *(float4*)&out[row * CEMB + col0 + 64 + tx * 4] = o1;
    }
}

// ---------------------------------------------------------------------------
extern "C" void kernel_launch(void* const* d_in, const int* in_sizes, int n_in,
                              void* d_out, int out_size)
{
    const float* x  = (const float*)d_in[0];
    const float* Wq = (const float*)d_in[1];
    const float* bq = (const float*)d_in[2];
    const float* Wk = (const float*)d_in[3];
    const float* bk = (const float*)d_in[4];
    const float* Wv = (const float*)d_in[5];
    const float* bv = (const float*)d_in[6];
    const float* Wp = (const float*)d_in[7];
    const float* bp = (const float*)d_in[8];
    float* out = (float*)d_out;

    cudaFuncSetAttribute(qkv_gemm,
                         cudaFuncAttributeMaxDynamicSharedMemorySize, GSMEM);
    cudaFuncSetAttribute(proj_gemm,
                         cudaFuncAttributeMaxDynamicSharedMemorySize, GSMEM);
    cudaFuncSetAttribute(attn_kernel,
                         cudaFuncAttributeMaxDynamicSharedMemorySize, ATTN_SMEM);

    qkv_gemm<<<dim3(CEMB / 128, BROWS / 128, 3), 256, GSMEM>>>(
        x, Wq, bq, Wk, bk, Wv, bv);
    attn_kernel<<<dim3(TSEQ / 128, 2 * NH), 256, ATTN_SMEM>>>();
    proj_gemm<<<dim3(CEMB / 128, BROWS / 128), 256, GSMEM>>>(Wp, bp, out);
}

// round 17
// speedup vs baseline: 2.4610x; 1.1674x over previous
#include <cuda_runtime.h>
#include <cuda_bf16.h>
#include <mma.h>
#include <math.h>

using namespace nvcuda;
typedef unsigned long long u64;
typedef __nv_bfloat16 bf16;

// ---------------------------------------------------------------------------
// CausalSelfAttention  B=2,T=2048,C=1024,nh=16,hs=64
// R16 (= R15 + asm constraint fix): pre-split fp32 -> (hi,lo) bf16 ONCE
// (prep kernel). All GEMMs are pure split-bf16 wmma (3 passes: hh+hl+lh)
// with cp.async staging, 2 CTAs/SM. qkv epilogue emits split q/k/v
// (Q pre-scaled); attn emits split y.
// ---------------------------------------------------------------------------

#define NH     16
#define HS     64
#define TSEQ   2048
#define CEMB   1024
#define BROWS  4096
#define LN1E4  9.210340371976184f
#define LDK    40                         // GEMM stage leading dim (bf16)
#define CLD    132                        // epilogue C smem stride (fp32)
#define MATB   (128 * LDK * 2)            // 10240 B per stage matrix
#define STAGE_BYTES (4 * MATB)            // Ah|Al|Bh|Bl = 40960
#define GSMEM  (2 * STAGE_BYTES)          // 81920 (>= 128*CLD*4 epilogue)

// ---- attention smem (bytes) ----
#define QLD    72
#define KLD    72
#define SLD    68
#define AQ_H   0
#define AQ_L   (AQ_H + 128 * QLD * 2)     // 18432
#define AKV0   (AQ_L + 128 * QLD * 2)     // 36864
#define KVMAT  (64 * KLD * 2)             // 9216
#define AKVSZ  (4 * KVMAT)                // 36864 per buffer
#define ASS    (AKV0 + 2 * AKVSZ)         // 110592
#define APH    (ASS + 128 * SLD * 4)      // 145408
#define APL    (APH + 128 * QLD * 2)      // 163840
#define ALS    (APL + 128 * QLD * 2)      // 182272
#define ATTN_SMEM (ALS + 512)             // 182784

// ---------------------------------------------------------------------------
// Split-bf16 scratch (allocation-free __device__ globals)
// ---------------------------------------------------------------------------
__device__ __align__(16) bf16 g_xh[BROWS * CEMB], g_xl[BROWS * CEMB];
__device__ __align__(16) bf16 g_wqh[CEMB * CEMB], g_wql[CEMB * CEMB];
__device__ __align__(16) bf16 g_wkh[CEMB * CEMB], g_wkl[CEMB * CEMB];
__device__ __align__(16) bf16 g_wvh[CEMB * CEMB], g_wvl[CEMB * CEMB];
__device__ __align__(16) bf16 g_wph[CEMB * CEMB], g_wpl[CEMB * CEMB];
__device__ __align__(16) bf16 g_qh[2 * NH * TSEQ * HS], g_ql[2 * NH * TSEQ * HS];
__device__ __align__(16) bf16 g_kh[2 * NH * TSEQ * HS], g_kl[2 * NH * TSEQ * HS];
__device__ __align__(16) bf16 g_vh[2 * NH * TSEQ * HS], g_vl[2 * NH * TSEQ * HS];
__device__ __align__(16) bf16 g_yh[2 * TSEQ * CEMB],   g_yl[2 * TSEQ * CEMB];

// ---- helpers --------------------------------------------------------------
__device__ __forceinline__ unsigned cvt2(float x0, float x1) {
    unsigned u;
    asm("cvt.rn.bf16x2.f32 %0, %1, %2;" : "=r"(u) : "f"(x1), "f"(x0));
    return u;
}
__device__ __forceinline__ void cvt4(float a, float b, float c, float d,
                                     u64& H, u64& L) {
    unsigned h0 = cvt2(a, b), h1 = cvt2(c, d);
    float r0 = a - __uint_as_float(h0 << 16);
    float r1 = b - __uint_as_float(h0 & 0xffff0000u);
    float r2 = c - __uint_as_float(h1 << 16);
    float r3 = d - __uint_as_float(h1 & 0xffff0000u);
    unsigned l0 = cvt2(r0, r1), l1 = cvt2(r2, r3);
    H = (u64)h0 | ((u64)h1 << 32);
    L = (u64)l0 | ((u64)l1 << 32);
}
// 16 fp32 -> split bf16, 16B stores to H/L at elem offset off
__device__ __forceinline__ void cvtstore16(const float4* v, bf16* H, bf16* L,
                                           int off) {
    u64 h0, l0, h1, l1, h2, l2, h3, l3;
    cvt4(v[0].x, v[0].y, v[0].z, v[0].w, h0, l0);
    cvt4(v[1].x, v[1].y, v[1].z, v[1].w, h1, l1);
    cvt4(v[2].x, v[2].y, v[2].z, v[2].w, h2, l2);
    cvt4(v[3].x, v[3].y, v[3].z, v[3].w, h3, l3);
    *(ulonglong2*)(H + off)     = make_ulonglong2(h0, h1);
    *(ulonglong2*)(H + off + 8) = make_ulonglong2(h2, h3);
    *(ulonglong2*)(L + off)     = make_ulonglong2(l0, l1);
    *(ulonglong2*)(L + off + 8) = make_ulonglong2(l2, l3);
}
__device__ __forceinline__ unsigned s2u(const void* p) {
    unsigned a;
    asm("{ .reg .u64 t; cvta.to.shared.u64 t, %1; cvt.u32.u64 %0, t; }"
        : "=r"(a) : "l"(p));
    return a;
}
__device__ __forceinline__ void cpa16(unsigned dst, const void* src) {
    asm volatile("cp.async.cg.shared.global [%0], [%1], 16;"
                 :: "r"(dst), "l"(src));
}
#define CPA_COMMIT() asm volatile("cp.async.commit_group;")
#define CPA_WAIT(n)  asm volatile("cp.async.wait_group %0;" :: "n"(n))

// ---------------------------------------------------------------------------
// Kernel 0: split fp32 -> (hi, lo) bf16 for x and the 4 weight matrices.
// ---------------------------------------------------------------------------
__global__ __launch_bounds__(256) void prep_split(
    const float* __restrict__ x,  const float* __restrict__ Wq,
    const float* __restrict__ Wk, const float* __restrict__ Wv,
    const float* __restrict__ Wp)
{
    const int z = blockIdx.z;
    const float* src; bf16 *H, *L; int n4;
    if (z == 0)      { src = x;  H = g_xh;  L = g_xl;  n4 = BROWS * CEMB / 4; }
    else if (z == 1) { src = Wq; H = g_wqh; L = g_wql; n4 = CEMB * CEMB / 4; }
    else if (z == 2) { src = Wk; H = g_wkh; L = g_wkl; n4 = CEMB * CEMB / 4; }
    else if (z == 3) { src = Wv; H = g_wvh; L = g_wvl; n4 = CEMB * CEMB / 4; }
    else             { src = Wp; H = g_wph; L = g_wpl; n4 = CEMB * CEMB / 4; }

    for (int i = blockIdx.x * blockDim.x + threadIdx.x; i < n4;
         i += gridDim.x * blockDim.x) {
        float4 v = ((const float4*)src)[i];
        u64 h, l;
        cvt4(v.x, v.y, v.z, v.w, h, l);
        *(u64*)&H[4 * i] = h;
        *(u64*)&L[4 * i] = l;
    }
}

// ---------------------------------------------------------------------------
// Shared split-bf16 wmma mainloop with cp.async staging.
// C[r,c] = sum_k A[r,k]*B[c,k]; result left in smem Cs (CLD stride).
// 128x128 tile, BK=32, 256 threads (8 warps 4x2).
// ---------------------------------------------------------------------------
__device__ __forceinline__ void gemm_ml(
    char* smemc,
    const bf16* __restrict__ Ah, const bf16* __restrict__ Al,
    const bf16* __restrict__ Bh, const bf16* __restrict__ Bl,
    int row0, int col0)
{
    const int tid = threadIdx.x;
    const int wid = tid >> 5;
    const int wr = wid >> 1, wc = wid & 1;

    // staging: thread covers rows r1, r1+64 at k-offset k1 in all 4 matrices
    const int r1 = tid >> 2;
    const int k1 = (tid & 3) * 8;
    const bf16* pah = Ah + (size_t)(row0 + r1) * CEMB + k1;
    const bf16* pal = Al + (size_t)(row0 + r1) * CEMB + k1;
    const bf16* pbh = Bh + (size_t)(col0 + r1) * CEMB + k1;
    const bf16* pbl = Bl + (size_t)(col0 + r1) * CEMB + k1;
    const unsigned sb = s2u(smemc) + r1 * 80 + k1 * 2;

    wmma::fragment<wmma::accumulator, 16, 16, 16, float> acc[2][4];
    #pragma unroll
    for (int i = 0; i < 2; i++)
        #pragma unroll
        for (int j = 0; j < 4; j++) wmma::fill_fragment(acc[i][j], 0.0f);

    // prologue: stage 0
    {
        unsigned d = sb;
        cpa16(d,                 pah); cpa16(d + 64 * 80,            pah + 64 * CEMB);
        cpa16(d + MATB,          pal); cpa16(d + MATB + 64 * 80,     pal + 64 * CEMB);
        cpa16(d + 2 * MATB,      pbh); cpa16(d + 2 * MATB + 64 * 80, pbh + 64 * CEMB);
        cpa16(d + 3 * MATB,      pbl); cpa16(d + 3 * MATB + 64 * 80, pbl + 64 * CEMB);
        CPA_COMMIT();
    }

    int buf = 0;
    #pragma unroll 1
    for (int kc = 0; kc < CEMB; kc += 32) {
        CPA_WAIT(0);
        __syncthreads();                       // stage(kc) visible to all
        const bool more = (kc + 32 < CEMB);
        if (more) {                            // stage(kc+32) -> other buffer
            unsigned d = sb + (buf ^ 1) * STAGE_BYTES;
            int kn = kc + 32;
            cpa16(d,                 pah + kn); cpa16(d + 64 * 80,            pah + 64 * CEMB + kn);
            cpa16(d + MATB,          pal + kn); cpa16(d + MATB + 64 * 80,     pal + 64 * CEMB + kn);
            cpa16(d + 2 * MATB,      pbh + kn); cpa16(d + 2 * MATB + 64 * 80, pbh + 64 * CEMB + kn);
            cpa16(d + 3 * MATB,      pbl + kn); cpa16(d + 3 * MATB + 64 * 80, pbl + 64 * CEMB + kn);
            CPA_COMMIT();
        }
        const bf16* As_h = (const bf16*)(smemc + buf * STAGE_BYTES);
        const bf16* As_l = As_h + 128 * LDK;
        const bf16* Bs_h = As_l + 128 * LDK;
        const bf16* Bs_l = Bs_h + 128 * LDK;

        #pragma unroll
        for (int ks = 0; ks < 2; ks++) {
            wmma::fragment<wmma::matrix_a, 16, 16, 16, bf16, wmma::row_major> ah[2], al[2];
            #pragma unroll
            for (int i = 0; i < 2; i++) {
                wmma::load_matrix_sync(ah[i], As_h + (wr * 32 + i * 16) * LDK + ks * 16, LDK);
                wmma::load_matrix_sync(al[i], As_l + (wr * 32 + i * 16) * LDK + ks * 16, LDK);
            }
            #pragma unroll
            for (int jh = 0; jh < 2; jh++) {   // b-frags in pairs (reg cap)
                wmma::fragment<wmma::matrix_b, 16, 16, 16, bf16, wmma::col_major> bh[2], bl[2];
                #pragma unroll
                for (int j = 0; j < 2; j++) {
                    int cj = wc * 64 + (jh * 2 + j) * 16;
                    wmma::load_matrix_sync(bh[j], Bs_h + cj * LDK + ks * 16, LDK);
                    wmma::load_matrix_sync(bl[j], Bs_l + cj * LDK + ks * 16, LDK);
                }
                #pragma unroll
                for (int i = 0; i < 2; i++)
                    #pragma unroll
                    for (int j = 0; j < 2; j++) {
                        wmma::mma_sync(acc[i][jh * 2 + j], ah[i], bh[j], acc[i][jh * 2 + j]);
                        wmma::mma_sync(acc[i][jh * 2 + j], ah[i], bl[j], acc[i][jh * 2 + j]);
                        wmma::mma_sync(acc[i][jh * 2 + j], al[i], bh[j], acc[i][jh * 2 + j]);
                    }
            }
        }
        __syncthreads();                       // all reads of buf done
        buf ^= 1;
    }

    float* Cs = (float*)smemc;
    #pragma unroll
    for (int i = 0; i < 2; i++)
        #pragma unroll
        for (int j = 0; j < 4; j++)
            wmma::store_matrix_sync(&Cs[(wr * 32 + i * 16) * CLD + wc * 64 + j * 16],
                                    acc[i][j], CLD, wmma::mem_row_major);
    __syncthreads();
}

// ---------------------------------------------------------------------------
// Kernel 1: QKV projection. Epilogue: bias + RoPE, write SPLIT q/k/v
// in (b,h,t,d); Q pre-scaled by 1/8.
// ---------------------------------------------------------------------------
__global__ __launch_bounds__(256, 2) void qkv_gemm(
    const float* __restrict__ bq, const float* __restrict__ bk,
    const float* __restrict__ bv)
{
    extern __shared__ __align__(16) char smemc[];
    const int z = blockIdx.z;
    const bf16* Wh  = (z == 0) ? g_wqh : (z == 1) ? g_wkh : g_wvh;
    const bf16* Wl  = (z == 0) ? g_wql : (z == 1) ? g_wkl : g_wvl;
    const float* bias = (z == 0) ? bq : (z == 1) ? bk : bv;
    bf16* Ho = (z == 0) ? g_qh : (z == 1) ? g_kh : g_vh;
    bf16* Lo = (z == 0) ? g_ql : (z == 1) ? g_kl : g_vl;

    const int row0 = blockIdx.y * 128;
    const int col0 = blockIdx.x * 128;

    gemm_ml(smemc, g_xh, g_xl, Wh, Wl, row0, col0);
    const float* Cs = (const float*)smemc;

    const int tid = threadIdx.x;
    const int tx = tid & 15, ty = tid >> 4;
    const int d0 = tx * 4;
    const int h0 = blockIdx.x * 2;

    float4 bb0 = *(const float4*)&bias[col0 + d0];
    float4 bb1 = *(const float4*)&bias[col0 + 64 + d0];
    float bvv[8] = {bb0.x, bb0.y, bb0.z, bb0.w, bb1.x, bb1.y, bb1.z, bb1.w};

    float th0 = 0.f, th1 = 0.f;
    if (z < 2) {
        th0 = expf(-((float)d0)       * (LN1E4 / 64.0f));
        th1 = expf(-((float)(d0 + 2)) * (LN1E4 / 64.0f));
    }
    const float sc = (z == 0) ? 0.125f : 1.0f;

    #pragma unroll
    for (int r8 = 0; r8 < 8; r8++) {
        int rl = ty * 8 + r8;
        int row = row0 + rl;
        int b = row >> 11;
        int t = row & 2047;
        float4 c0 = *(const float4*)&Cs[rl * CLD + d0];
        float4 c1 = *(const float4*)&Cs[rl * CLD + 64 + d0];
        float v[8] = {c0.x + bvv[0], c0.y + bvv[1], c0.z + bvv[2], c0.w + bvv[3],
                      c1.x + bvv[4], c1.y + bvv[5], c1.z + bvv[6], c1.w + bvv[7]};
        if (z < 2) {
            float cc0, ss0, cc1, ss1;
            sincosf((float)t * th0, &ss0, &cc0);
            sincosf((float)t * th1, &ss1, &cc1);
            float r0 = v[0] * cc0 - v[1] * ss0, r1 = v[0] * ss0 + v[1] * cc0;
            float r2 = v[2] * cc1 - v[3] * ss1, r3 = v[2] * ss1 + v[3] * cc1;
            float r4 = v[4] * cc0 - v[5] * ss0, r5 = v[4] * ss0 + v[5] * cc0;
            float r6 = v[6] * cc1 - v[7] * ss1, r7 = v[6] * ss1 + v[7] * cc1;
            v[0] = r0; v[1] = r1; v[2] = r2; v[3] = r3;
            v[4] = r4; v[5] = r5; v[6] = r6; v[7] = r7;
        }
        u64 H, L;
        size_t o0 = (((size_t)b * NH + h0) * TSEQ + t) * HS + d0;
        cvt4(v[0] * sc, v[1] * sc, v[2] * sc, v[3] * sc, H, L);
        *(u64*)&Ho[o0] = H; *(u64*)&Lo[o0] = L;
        size_t o1 = (((size_t)b * NH + h0 + 1) * TSEQ + t) * HS + d0;
        cvt4(v[4] * sc, v[5] * sc, v[6] * sc, v[7] * sc, H, L);
        *(u64*)&Ho[o1] = H; *(u64*)&Lo[o1] = L;
    }
}

// ---------------------------------------------------------------------------
// Kernel 2: flash attention, split-bf16 wmma, no-max softmax.
// Br=128, Bc=64, 256 threads (8 warps 4x2). Q/K/V pre-split in gmem.
// ---------------------------------------------------------------------------
__global__ __launch_bounds__(256) void attn_kernel()
{
    extern __shared__ __align__(16) char smc[];
    bf16* QH = (bf16*)(smc + AQ_H);
    bf16* QL = (bf16*)(smc + AQ_L);
    float* SS = (float*)(smc + ASS);
    bf16* PH = (bf16*)(smc + APH);
    bf16* PL = (bf16*)(smc + APL);
    float* Ls = (float*)(smc + ALS);

    const int tid = threadIdx.x;
    const int wid = tid >> 5;
    const int wr = wid >> 1, wc = wid & 1;
    const int qt = (gridDim.x - 1) - blockIdx.x;
    const int bh = blockIdx.y;

    const bf16* qph = g_qh + (size_t)bh * TSEQ * HS;
    const bf16* qpl = g_ql + (size_t)bh * TSEQ * HS;
    const bf16* kph = g_kh + (size_t)bh * TSEQ * HS;
    const bf16* kpl = g_kl + (size_t)bh * TSEQ * HS;
    const bf16* vph = g_vh + (size_t)bh * TSEQ * HS;
    const bf16* vpl = g_vl + (size_t)bh * TSEQ * HS;

    const int q0 = qt * 128;

    // per-thread staging coords
    const int rk = tid >> 3;              // 0..31
    const int k8 = (tid & 7) * 8;         // 0..56
    const unsigned skv = s2u(smc + AKV0) + rk * 144 + k8 * 2;

    // prologue: Q (both halves) + KV tile 0, one group
    {
        unsigned sq = s2u(smc + AQ_H) + rk * 144 + k8 * 2;
        #pragma unroll
        for (int i = 0; i < 4; i++) {      // Q rows rk, rk+32, rk+64, rk+96
            int r = rk + 32 * i;
            cpa16(sq + 32 * i * 144,                 qph + (size_t)(q0 + r) * HS + k8);
            cpa16(sq + 32 * i * 144 + 128 * QLD * 2, qpl + (size_t)(q0 + r) * HS + k8);
        }
        #pragma unroll
        for (int i = 0; i < 2; i++) {      // KV rows rk, rk+32
            int r = rk + 32 * i;
            unsigned d = skv + 32 * i * 144;
            cpa16(d,             kph + (size_t)r * HS + k8);
            cpa16(d + KVMAT,     kpl + (size_t)r * HS + k8);
            cpa16(d + 2 * KVMAT, vph + (size_t)r * HS + k8);
            cpa16(d + 3 * KVMAT, vpl + (size_t)r * HS + k8);
        }
        CPA_COMMIT();
    }

    wmma::fragment<wmma::accumulator, 16, 16, 16, float> of[2][2];
    #pragma unroll
    for (int i = 0; i < 2; i++)
        #pragma unroll
        for (int j = 0; j < 2; j++) wmma::fill_fragment(of[i][j], 0.0f);
    float lpart = 0.0f;

    const int er = tid >> 1;
    const int ec = (tid & 1) * 32;
    const int ktmax = 2 * qt + 1;
    int buf = 0;

    #pragma unroll 1
    for (int kt = 0; kt <= ktmax; kt++) {
        CPA_WAIT(0);
        __syncthreads();                   // KV(kt) [+Q] visible

        if (kt < ktmax) {                  // stage KV(kt+1) into buf^1
            const int kn = (kt + 1) * 64;
            unsigned db = skv + (buf ^ 1) * AKVSZ;
            #pragma unroll
            for (int i = 0; i < 2; i++) {
                int r = kn + rk + 32 * i;
                unsigned d = db + 32 * i * 144;
                cpa16(d,             kph + (size_t)r * HS + k8);
                cpa16(d + KVMAT,     kpl + (size_t)r * HS + k8);
                cpa16(d + 2 * KVMAT, vph + (size_t)r * HS + k8);
                cpa16(d + 3 * KVMAT, vpl + (size_t)r * HS + k8);
            }
            CPA_COMMIT();
        }

        const bf16* KH = (const bf16*)(smc + AKV0 + buf * AKVSZ);
        const bf16* KL = KH + 64 * KLD;
        const bf16* VH = KL + 64 * KLD;
        const bf16* VL = VH + 64 * KLD;

        // ---- S = (Q/8) K^T (split, 3 passes) ----
        wmma::fragment<wmma::accumulator, 16, 16, 16, float> sacc[2][2];
        #pragma unroll
        for (int i = 0; i < 2; i++)
            #pragma unroll
            for (int j = 0; j < 2; j++) wmma::fill_fragment(sacc[i][j], 0.0f);
        #pragma unroll
        for (int ds = 0; ds < 4; ds++) {
            wmma::fragment<wmma::matrix_a, 16, 16, 16, bf16, wmma::row_major> ah[2], al[2];
            wmma::fragment<wmma::matrix_b, 16, 16, 16, bf16, wmma::col_major> bh[2], bl[2];
            #pragma unroll
            for (int i = 0; i < 2; i++) {
                wmma::load_matrix_sync(ah[i], QH + (wr * 32 + i * 16) * QLD + ds * 16, QLD);
                wmma::load_matrix_sync(al[i], QL + (wr * 32 + i * 16) * QLD + ds * 16, QLD);
            }
            #pragma unroll
            for (int j = 0; j < 2; j++) {
                wmma::load_matrix_sync(bh[j], KH + (wc * 32 + j * 16) * KLD + ds * 16, KLD);
                wmma::load_matrix_sync(bl[j], KL + (wc * 32 + j * 16) * KLD + ds * 16, KLD);
            }
            #pragma unroll
            for (int i = 0; i < 2; i++)
                #pragma unroll
                for (int j = 0; j < 2; j++) {
                    wmma::mma_sync(sacc[i][j], ah[i], bh[j], sacc[i][j]);
                    wmma::mma_sync(sacc[i][j], ah[i], bl[j], sacc[i][j]);
                    wmma::mma_sync(sacc[i][j], al[i], bh[j], sacc[i][j]);
                }
        }
        #pragma unroll
        for (int i = 0; i < 2; i++)
            #pragma unroll
            for (int j = 0; j < 2; j++)
                wmma::store_matrix_sync(&SS[(wr * 32 + i * 16) * SLD + wc * 32 + j * 16],
                                        sacc[i][j], SLD, wmma::mem_row_major);
        __syncthreads();

        // ---- exp (no max), causal mask, l accumulate, split P ----
        {
            const int k0 = kt * 64;
            const bool diag = (kt >= 2 * qt);
            const int gr = q0 + er;
            float e[32];
            #pragma unroll
            for (int q = 0; q < 8; q++) {
                float4 s4 = *(const float4*)&SS[er * SLD + ec + 4 * q];
                float s[4] = {s4.x, s4.y, s4.z, s4.w};
                #pragma unroll
                for (int m = 0; m < 4; m++) {
                    int jj = 4 * q + m;
                    bool ok = !diag || (k0 + ec + jj <= gr);
                    float ev = ok ? __expf(s[m]) : 0.0f;
                    e[jj] = ev;
                    lpart += ev;
                }
            }
            #pragma unroll
            for (int h = 0; h < 2; h++) {
                float4 v[4];
                #pragma unroll
                for (int q = 0; q < 4; q++)
                    v[q] = make_float4(e[16 * h + 4 * q], e[16 * h + 4 * q + 1],
                                       e[16 * h + 4 * q + 2], e[16 * h + 4 * q + 3]);
                cvtstore16(v, PH, PL, er * QLD + ec + 16 * h);
            }
        }
        __syncthreads();

        // ---- O += P V (split, 3 passes) ----
        #pragma unroll
        for (int ks = 0; ks < 4; ks++) {
            wmma::fragment<wmma::matrix_a, 16, 16, 16, bf16, wmma::row_major> ph[2], pl[2];
            wmma::fragment<wmma::matrix_b, 16, 16, 16, bf16, wmma::row_major> vh[2], vl[2];
            #pragma unroll
            for (int i = 0; i < 2; i++) {
                wmma::load_matrix_sync(ph[i], PH + (wr * 32 + i * 16) * QLD + ks * 16, QLD);
                wmma::load_matrix_sync(pl[i], PL + (wr * 32 + i * 16) * QLD + ks * 16, QLD);
            }
            #pragma unroll
            for (int j = 0; j < 2; j++) {
                wmma::load_matrix_sync(vh[j], VH + (ks * 16) * KLD + wc * 32 + j * 16, KLD);
                wmma::load_matrix_sync(vl[j], VL + (ks * 16) * KLD + wc * 32 + j * 16, KLD);
            }
            #pragma unroll
            for (int i = 0; i < 2; i++)
                #pragma unroll
                for (int j = 0; j < 2; j++) {
                    wmma::mma_sync(of[i][j], ph[i], vh[j], of[i][j]);
                    wmma::mma_sync(of[i][j], ph[i], vl[j], of[i][j]);
                    wmma::mma_sync(of[i][j], pl[i], vh[j], of[i][j]);
                }
        }
        __syncthreads();                   // buf reads done
        buf ^= 1;
    }

    // ---- epilogue: O -> SS, l -> Ls, normalize, write SPLIT y ----
    #pragma unroll
    for (int i = 0; i < 2; i++)
        #pragma unroll
        for (int j = 0; j < 2; j++)
            wmma::store_matrix_sync(&SS[(wr * 32 + i * 16) * SLD + wc * 32 + j * 16],
                                    of[i][j], SLD, wmma::mem_row_major);
    {
        float lr = lpart + __shfl_xor_sync(0xffffffffu, lpart, 1);
        if ((tid & 1) == 0) Ls[er] = lr;
    }
    __syncthreads();

    {
        const int b = bh >> 4, h = bh & 15;
        const float inv = 1.0f / Ls[er];
        const size_t yo = ((size_t)b * TSEQ + q0 + er) * CEMB + h * HS + ec;
        #pragma unroll
        for (int hh = 0; hh < 2; hh++) {
            float4 v[4];
            #pragma unroll
            for (int q = 0; q < 4; q++) {
                float4 o = *(const float4*)&SS[er * SLD + ec + 16 * hh + 4 * q];
                v[q] = make_float4(o.x * inv, o.y * inv, o.z * inv, o.w * inv);
            }
            cvtstore16(v, g_yh, g_yl, (int)(yo + 16 * hh));
        }
    }
}

// ---------------------------------------------------------------------------
// Kernel 3: output projection, bias epilogue to fp32 out.
// ---------------------------------------------------------------------------
__global__ __launch_bounds__(256, 2) void proj_gemm(
    const float* __restrict__ bp, float* __restrict__ out)
{
    extern __shared__ __align__(16) char smemc[];
    const int row0 = blockIdx.y * 128;
    const int col0 = blockIdx.x * 128;

    gemm_ml(smemc, g_yh, g_yl, g_wph, g_wpl, row0, col0);
    const float* Cs = (const float*)smemc;

    const int tid = threadIdx.x;
    const int tx = tid & 15, ty = tid >> 4;

    float4 bb0 = *(const float4*)&bp[col0 + tx * 4];
    float4 bb1 = *(const float4*)&bp[col0 + 64 + tx * 4];

    #pragma unroll
    for (int r8 = 0; r8 < 8; r8++) {
        int rl = ty * 8 + r8;
        size_t row = (size_t)(row0 + rl);
        float4 c0 = *(const float4*)&Cs[rl * CLD + tx * 4];
        float4 c1 = *(const float4*)&Cs[rl * CLD + 64 + tx * 4];
        float4 o0 = {c0.x + bb0.x, c0.y + bb0.y, c0.z + bb0.z, c0.w + bb0.w};
        float4 o1 = {c1.x + bb1.x, c1.y + bb1.y, c1.z + bb1.z, c1.w + bb1.w};
        *(float4*)&out[row * CEMB + col0 + tx * 4] = o0;
        *(float4*)&out[row * CEMB + col0 + 64 + tx * 4] = o1;
    }
}

// ---------------------------------------------------------------------------
extern "C" void kernel_launch(void* const* d_in, const int* in_sizes, int n_in,
                              void* d_out, int out_size)
{
    const float* x  = (const float*)d_in[0];
    const float* Wq = (const float*)d_in[1];
    const float* bq = (const float*)d_in[2];
    const float* Wk = (const float*)d_in[3];
    const float* bk = (const float*)d_in[4];
    const float* Wv = (const float*)d_in[5];
    const float* bv = (const float*)d_in[6];
    const float* Wp = (const float*)d_in[7];
    const float* bp = (const float*)d_in[8];
    float* out = (float*)d_out;

    cudaFuncSetAttribute(qkv_gemm,
                         cudaFuncAttributeMaxDynamicSharedMemorySize, GSMEM);
    cudaFuncSetAttribute(proj_gemm,
                         cudaFuncAttributeMaxDynamicSharedMemorySize, GSMEM);
    cudaFuncSetAttribute(attn_kernel,
                         cudaFuncAttributeMaxDynamicSharedMemorySize, ATTN_SMEM);

    prep_split<<<dim3(512, 1, 5), 256>>>(x, Wq, Wk, Wv, Wp);
    qkv_gemm<<<dim3(CEMB / 128, BROWS / 128, 3), 256, GSMEM>>>(bq, bk, bv);
    attn_kernel<<<dim3(TSEQ / 128, 2 * NH), 256, ATTN_SMEM>>>();
    proj_gemm<<<dim3(CEMB / 128, BROWS / 128), 256, GSMEM>>>(bp, out);
}